// round 2
// baseline (speedup 1.0000x reference)
#include <cuda_runtime.h>
#include <cstdint>

// Problem constants
// x: [B=2, E=512, S=128, L=128] fp32 ; W: [1536, 512] ; b: [1536]
// out: [2, 512, 128, 128] fp32
#define NB 2
#define NH 8
#define DH 64
#define NS 128
#define NL 128
// scratch layout: [b][h][s][l][d], d contiguous
#define QKV_ELEMS (NB * NH * NS * NL * DH)   // 16,777,216 floats = 64MB

__device__ __align__(256) float g_q[QKV_ELEMS];
__device__ __align__(256) float g_k[QKV_ELEMS];
__device__ __align__(256) float g_v[QKV_ELEMS];
__device__ __align__(256) float g_oc[QKV_ELEMS];

// ---------- helpers ----------
__device__ __forceinline__ uint32_t tf32u(float x) {
    uint32_t r;
    asm("cvt.rna.tf32.f32 %0, %1;" : "=r"(r) : "f"(x));
    return r;
}
__device__ __forceinline__ float tf32f(float x) { return __uint_as_float(tf32u(x)); }
__device__ __forceinline__ uint32_t fu(float x) { return __float_as_uint(x); }

__device__ __forceinline__ void mma8(float (&d)[4], const uint32_t (&a)[4], const uint32_t (&b)[2]) {
    asm volatile(
        "mma.sync.aligned.m16n8k8.row.col.f32.tf32.tf32.f32 "
        "{%0,%1,%2,%3}, {%4,%5,%6,%7}, {%8,%9}, {%0,%1,%2,%3};\n"
        : "+f"(d[0]), "+f"(d[1]), "+f"(d[2]), "+f"(d[3])
        : "r"(a[0]), "r"(a[1]), "r"(a[2]), "r"(a[3]), "r"(b[0]), "r"(b[1]));
}

// =====================================================================
// K1: QKV GEMM.  C[o, p] = sum_i W[o,i] * X[b][i][p] (+bias), p = s*128+l
// Block tile: 128 (o) x 128 (p=one s row, all l). K chunks of 32.
// Epilogue: transpose via smem, scatter to g_q/g_k/g_v [b][h][s][l][d].
// =====================================================================
#define K1_SMEM (128 * 129 * 4)   // Cs dominates (As+Bs = 2*32*132 floats fits under it)

__global__ void __launch_bounds__(256, 1) k_qkv(const float* __restrict__ X,
                                                const float* __restrict__ W,
                                                const float* __restrict__ bias) {
    extern __shared__ float sm[];
    float* As = sm;               // [32][132] k-major: As[k][m]
    float* Bs = sm + 32 * 132;    // [32][132]          Bs[k][n]
    const int tid = threadIdx.x;
    const int warp = tid >> 5, lane = tid & 31;
    const int g = lane >> 2, qc = lane & 3;
    const int wm = warp >> 2, wn = warp & 3;        // 2 x 4 warp grid
    const int o0 = blockIdx.x * 128;
    const int s = blockIdx.y;
    const int b = blockIdx.z;
    const float* Xb = X + (size_t)b * 512 * 16384 + (size_t)s * 128;

    float acc[4][4][4];
#pragma unroll
    for (int i = 0; i < 4; i++)
#pragma unroll
        for (int j = 0; j < 4; j++)
#pragma unroll
            for (int k = 0; k < 4; k++) acc[i][j][k] = 0.f;

    for (int kk = 0; kk < 512; kk += 32) {
        // Load W tile [128 o x 32 k] -> As[k][m], tf32-rounded
#pragma unroll
        for (int rep = 0; rep < 4; rep++) {
            int idx = rep * 256 + tid;        // 0..1023
            int r = idx >> 3;                 // 0..127 (o)
            int kq = (idx & 7) * 4;           // 0..28
            const float4 v = *reinterpret_cast<const float4*>(W + (size_t)(o0 + r) * 512 + kk + kq);
            As[(kq + 0) * 132 + r] = tf32f(v.x);
            As[(kq + 1) * 132 + r] = tf32f(v.y);
            As[(kq + 2) * 132 + r] = tf32f(v.z);
            As[(kq + 3) * 132 + r] = tf32f(v.w);
        }
        // Load X tile [32 k x 128 n] -> Bs[k][n]
#pragma unroll
        for (int rep = 0; rep < 4; rep++) {
            int idx = rep * 256 + tid;
            int r = idx >> 5;                 // 0..31 (k)
            int c4 = (idx & 31) * 4;          // 0..124
            const float4 v = *reinterpret_cast<const float4*>(Xb + (size_t)(kk + r) * 16384 + c4);
            float4 w4 = make_float4(tf32f(v.x), tf32f(v.y), tf32f(v.z), tf32f(v.w));
            *reinterpret_cast<float4*>(&Bs[r * 132 + c4]) = w4;
        }
        __syncthreads();
#pragma unroll
        for (int k0 = 0; k0 < 32; k0 += 8) {
            uint32_t af[4][4], bf[4][2];
#pragma unroll
            for (int mt = 0; mt < 4; mt++) {
                int m = wm * 64 + mt * 16 + g;
                af[mt][0] = fu(As[(k0 + qc) * 132 + m]);
                af[mt][1] = fu(As[(k0 + qc) * 132 + m + 8]);
                af[mt][2] = fu(As[(k0 + qc + 4) * 132 + m]);
                af[mt][3] = fu(As[(k0 + qc + 4) * 132 + m + 8]);
            }
#pragma unroll
            for (int nt = 0; nt < 4; nt++) {
                int n = wn * 32 + nt * 8 + g;
                bf[nt][0] = fu(Bs[(k0 + qc) * 132 + n]);
                bf[nt][1] = fu(Bs[(k0 + qc + 4) * 132 + n]);
            }
#pragma unroll
            for (int mt = 0; mt < 4; mt++)
#pragma unroll
                for (int nt = 0; nt < 4; nt++) mma8(acc[mt][nt], af[mt], bf[nt]);
        }
        __syncthreads();
    }

    // Stage C tile [128 o][128 l] into smem for transposed scatter
    float* Cs = sm;   // [128][129]
#pragma unroll
    for (int mt = 0; mt < 4; mt++)
#pragma unroll
        for (int nt = 0; nt < 4; nt++) {
            int r = wm * 64 + mt * 16 + g;
            int n = wn * 32 + nt * 8 + 2 * qc;
            Cs[r * 129 + n] = acc[mt][nt][0];
            Cs[r * 129 + n + 1] = acc[mt][nt][1];
            Cs[(r + 8) * 129 + n] = acc[mt][nt][2];
            Cs[(r + 8) * 129 + n + 1] = acc[mt][nt][3];
        }
    __syncthreads();

    const int sel = o0 >> 9;                 // 0=q 1=k 2=v
    const int h0 = (o0 & 511) >> 6;          // tile covers heads h0, h0+1
    float* dst = (sel == 0) ? g_q : ((sel == 1) ? g_k : g_v);
    const float scale = (sel == 0) ? 0.125f : 1.0f;   // DH^-0.5
#pragma unroll
    for (int rep = 0; rep < 16; rep++) {
        int idx = rep * 256 + tid;           // 0..4095 float4s
        int d4 = (idx & 15) * 4;             // 0..60
        int l = (idx >> 4) & 127;
        int hh = idx >> 11;                  // 0..1
        int od = hh * 64 + d4;
        float4 v;
        v.x = (Cs[(od + 0) * 129 + l] + bias[o0 + od + 0]) * scale;
        v.y = (Cs[(od + 1) * 129 + l] + bias[o0 + od + 1]) * scale;
        v.z = (Cs[(od + 2) * 129 + l] + bias[o0 + od + 2]) * scale;
        v.w = (Cs[(od + 3) * 129 + l] + bias[o0 + od + 3]) * scale;
        size_t da = (((size_t)((b * 8 + h0 + hh) * 128 + s)) * 128 + l) * 64 + d4;
        *reinterpret_cast<float4*>(dst + da) = v;
    }
}

// =====================================================================
// Attention core shared structure (written out twice):
// 128 (seq) x 128 (seq) x 64 (d) attention per CTA, 8 warps.
// Warp w owns score rows 16w..16w+15.
// =====================================================================
#define ATTN_SMEM ((3 * 128 * 68 + 128 * 132) * 4)   // 172,032 B

// K2: column attention. Block = (l, h, b). Writes g_oc[b][h][s][l][d].
__global__ void __launch_bounds__(256, 1) k_colattn() {
    extern __shared__ float sm[];
    float* Qs = sm;                   // [128][68]
    float* Ks = sm + 128 * 68;
    float* Vs = sm + 2 * 128 * 68;
    float* Ps = sm + 3 * 128 * 68;    // [128][132]
    float* Os = sm;                   // overlay on Qs: [128][68]
    const int tid = threadIdx.x;
    const int warp = tid >> 5, lane = tid & 31;
    const int g = lane >> 2, qc = lane & 3;
    const int l = blockIdx.x, h = blockIdx.y, b = blockIdx.z;
    const size_t base = (size_t)((b * 8 + h) * 128) * 8192;   // + s*8192 + l*64 + d

    // Gather Q,K,V tiles [s][d] for this column l (256B rows, coalesced)
#pragma unroll
    for (int rep = 0; rep < 8; rep++) {
        int idx = rep * 256 + tid;           // 0..2047
        int s = idx >> 4;
        int d4 = (idx & 15) * 4;
        size_t ga = base + (size_t)s * 8192 + (size_t)l * 64 + d4;
        float4 q4 = *reinterpret_cast<const float4*>(g_q + ga);
        float4 k4 = *reinterpret_cast<const float4*>(g_k + ga);
        float4 v4 = *reinterpret_cast<const float4*>(g_v + ga);
        int so = s * 68 + d4;
        *reinterpret_cast<float4*>(&Qs[so]) = make_float4(tf32f(q4.x), tf32f(q4.y), tf32f(q4.z), tf32f(q4.w));
        *reinterpret_cast<float4*>(&Ks[so]) = make_float4(tf32f(k4.x), tf32f(k4.y), tf32f(k4.z), tf32f(k4.w));
        *reinterpret_cast<float4*>(&Vs[so]) = make_float4(tf32f(v4.x), tf32f(v4.y), tf32f(v4.z), tf32f(v4.w));
    }
    __syncthreads();

    // scores[s][t] = sum_d Q[s][d] * K[t][d]
    float sc[16][4];
#pragma unroll
    for (int nt = 0; nt < 16; nt++)
#pragma unroll
        for (int k = 0; k < 4; k++) sc[nt][k] = 0.f;
    const int row = warp * 16;
#pragma unroll
    for (int k0 = 0; k0 < 64; k0 += 8) {
        uint32_t a[4];
        a[0] = fu(Qs[(row + g) * 68 + k0 + qc]);
        a[1] = fu(Qs[(row + g + 8) * 68 + k0 + qc]);
        a[2] = fu(Qs[(row + g) * 68 + k0 + qc + 4]);
        a[3] = fu(Qs[(row + g + 8) * 68 + k0 + qc + 4]);
#pragma unroll
        for (int nt = 0; nt < 16; nt++) {
            uint32_t bb[2];
            bb[0] = fu(Ks[(nt * 8 + g) * 68 + k0 + qc]);
            bb[1] = fu(Ks[(nt * 8 + g) * 68 + k0 + qc + 4]);
            mma8(sc[nt], a, bb);
        }
    }
    // softmax over t (each thread: rows {row+g, row+g+8}, 32 cols each)
    float m0 = -1e30f, m1 = -1e30f;
#pragma unroll
    for (int nt = 0; nt < 16; nt++) {
        m0 = fmaxf(m0, fmaxf(sc[nt][0], sc[nt][1]));
        m1 = fmaxf(m1, fmaxf(sc[nt][2], sc[nt][3]));
    }
    m0 = fmaxf(m0, __shfl_xor_sync(0xffffffffu, m0, 1));
    m0 = fmaxf(m0, __shfl_xor_sync(0xffffffffu, m0, 2));
    m1 = fmaxf(m1, __shfl_xor_sync(0xffffffffu, m1, 1));
    m1 = fmaxf(m1, __shfl_xor_sync(0xffffffffu, m1, 2));
    const float LOG2E = 1.4426950408889634f;
    float s0 = 0.f, s1 = 0.f;
#pragma unroll
    for (int nt = 0; nt < 16; nt++) {
        sc[nt][0] = exp2f((sc[nt][0] - m0) * LOG2E); s0 += sc[nt][0];
        sc[nt][1] = exp2f((sc[nt][1] - m0) * LOG2E); s0 += sc[nt][1];
        sc[nt][2] = exp2f((sc[nt][2] - m1) * LOG2E); s1 += sc[nt][2];
        sc[nt][3] = exp2f((sc[nt][3] - m1) * LOG2E); s1 += sc[nt][3];
    }
    s0 += __shfl_xor_sync(0xffffffffu, s0, 1);
    s0 += __shfl_xor_sync(0xffffffffu, s0, 2);
    s1 += __shfl_xor_sync(0xffffffffu, s1, 1);
    s1 += __shfl_xor_sync(0xffffffffu, s1, 2);
    const float inv0 = 1.0f / s0, inv1 = 1.0f / s1;
#pragma unroll
    for (int nt = 0; nt < 16; nt++) {
        int n = nt * 8 + 2 * qc;
        Ps[(row + g) * 132 + n] = tf32f(sc[nt][0] * inv0);
        Ps[(row + g) * 132 + n + 1] = tf32f(sc[nt][1] * inv0);
        Ps[(row + g + 8) * 132 + n] = tf32f(sc[nt][2] * inv1);
        Ps[(row + g + 8) * 132 + n + 1] = tf32f(sc[nt][3] * inv1);
    }
    __syncthreads();

    // out[s][d] = P[s][t] @ V[t][d]
    float oa[8][4];
#pragma unroll
    for (int nt = 0; nt < 8; nt++)
#pragma unroll
        for (int k = 0; k < 4; k++) oa[nt][k] = 0.f;
#pragma unroll
    for (int k0 = 0; k0 < 128; k0 += 8) {
        uint32_t a[4];
        a[0] = fu(Ps[(row + g) * 132 + k0 + qc]);
        a[1] = fu(Ps[(row + g + 8) * 132 + k0 + qc]);
        a[2] = fu(Ps[(row + g) * 132 + k0 + qc + 4]);
        a[3] = fu(Ps[(row + g + 8) * 132 + k0 + qc + 4]);
#pragma unroll
        for (int nt = 0; nt < 8; nt++) {
            uint32_t bb[2];
            bb[0] = fu(Vs[(k0 + qc) * 68 + nt * 8 + g]);
            bb[1] = fu(Vs[(k0 + qc + 4) * 68 + nt * 8 + g]);
            mma8(oa[nt], a, bb);
        }
    }
    __syncthreads();
#pragma unroll
    for (int nt = 0; nt < 8; nt++) {
        int n = nt * 8 + 2 * qc;
        Os[(row + g) * 68 + n] = oa[nt][0];
        Os[(row + g) * 68 + n + 1] = oa[nt][1];
        Os[(row + g + 8) * 68 + n] = oa[nt][2];
        Os[(row + g + 8) * 68 + n + 1] = oa[nt][3];
    }
    __syncthreads();
#pragma unroll
    for (int rep = 0; rep < 8; rep++) {
        int idx = rep * 256 + tid;
        int s = idx >> 4;
        int d4 = (idx & 15) * 4;
        float4 v = *reinterpret_cast<const float4*>(&Os[s * 68 + d4]);
        *reinterpret_cast<float4*>(g_oc + base + (size_t)s * 8192 + (size_t)l * 64 + d4) = v;
    }
}

// K3: row attention + add col result + write final output [B,512,S,L].
__global__ void __launch_bounds__(256, 1) k_rowattn(float* __restrict__ out) {
    extern __shared__ float sm[];
    float* Qs = sm;
    float* Ks = sm + 128 * 68;
    float* Vs = sm + 2 * 128 * 68;
    float* Ps = sm + 3 * 128 * 68;
    float* Os = sm;                  // [128][65] overlay
    const int tid = threadIdx.x;
    const int warp = tid >> 5, lane = tid & 31;
    const int g = lane >> 2, qc = lane & 3;
    const int s = blockIdx.x, h = blockIdx.y, b = blockIdx.z;
    const size_t rbase = (size_t)((b * 8 + h) * 128) * 8192 + (size_t)s * 8192;

    // Fully contiguous 32KB loads per tensor
#pragma unroll
    for (int rep = 0; rep < 8; rep++) {
        int idx = rep * 256 + tid;
        int l = idx >> 4;
        int d4 = (idx & 15) * 4;
        size_t ga = rbase + (size_t)idx * 4;
        float4 q4 = *reinterpret_cast<const float4*>(g_q + ga);
        float4 k4 = *reinterpret_cast<const float4*>(g_k + ga);
        float4 v4 = *reinterpret_cast<const float4*>(g_v + ga);
        int so = l * 68 + d4;
        *reinterpret_cast<float4*>(&Qs[so]) = make_float4(tf32f(q4.x), tf32f(q4.y), tf32f(q4.z), tf32f(q4.w));
        *reinterpret_cast<float4*>(&Ks[so]) = make_float4(tf32f(k4.x), tf32f(k4.y), tf32f(k4.z), tf32f(k4.w));
        *reinterpret_cast<float4*>(&Vs[so]) = make_float4(tf32f(v4.x), tf32f(v4.y), tf32f(v4.z), tf32f(v4.w));
    }
    __syncthreads();

    float sc[16][4];
#pragma unroll
    for (int nt = 0; nt < 16; nt++)
#pragma unroll
        for (int k = 0; k < 4; k++) sc[nt][k] = 0.f;
    const int row = warp * 16;
#pragma unroll
    for (int k0 = 0; k0 < 64; k0 += 8) {
        uint32_t a[4];
        a[0] = fu(Qs[(row + g) * 68 + k0 + qc]);
        a[1] = fu(Qs[(row + g + 8) * 68 + k0 + qc]);
        a[2] = fu(Qs[(row + g) * 68 + k0 + qc + 4]);
        a[3] = fu(Qs[(row + g + 8) * 68 + k0 + qc + 4]);
#pragma unroll
        for (int nt = 0; nt < 16; nt++) {
            uint32_t bb[2];
            bb[0] = fu(Ks[(nt * 8 + g) * 68 + k0 + qc]);
            bb[1] = fu(Ks[(nt * 8 + g) * 68 + k0 + qc + 4]);
            mma8(sc[nt], a, bb);
        }
    }
    float m0 = -1e30f, m1 = -1e30f;
#pragma unroll
    for (int nt = 0; nt < 16; nt++) {
        m0 = fmaxf(m0, fmaxf(sc[nt][0], sc[nt][1]));
        m1 = fmaxf(m1, fmaxf(sc[nt][2], sc[nt][3]));
    }
    m0 = fmaxf(m0, __shfl_xor_sync(0xffffffffu, m0, 1));
    m0 = fmaxf(m0, __shfl_xor_sync(0xffffffffu, m0, 2));
    m1 = fmaxf(m1, __shfl_xor_sync(0xffffffffu, m1, 1));
    m1 = fmaxf(m1, __shfl_xor_sync(0xffffffffu, m1, 2));
    const float LOG2E = 1.4426950408889634f;
    float s0 = 0.f, s1 = 0.f;
#pragma unroll
    for (int nt = 0; nt < 16; nt++) {
        sc[nt][0] = exp2f((sc[nt][0] - m0) * LOG2E); s0 += sc[nt][0];
        sc[nt][1] = exp2f((sc[nt][1] - m0) * LOG2E); s0 += sc[nt][1];
        sc[nt][2] = exp2f((sc[nt][2] - m1) * LOG2E); s1 += sc[nt][2];
        sc[nt][3] = exp2f((sc[nt][3] - m1) * LOG2E); s1 += sc[nt][3];
    }
    s0 += __shfl_xor_sync(0xffffffffu, s0, 1);
    s0 += __shfl_xor_sync(0xffffffffu, s0, 2);
    s1 += __shfl_xor_sync(0xffffffffu, s1, 1);
    s1 += __shfl_xor_sync(0xffffffffu, s1, 2);
    const float inv0 = 1.0f / s0, inv1 = 1.0f / s1;
#pragma unroll
    for (int nt = 0; nt < 16; nt++) {
        int n = nt * 8 + 2 * qc;
        Ps[(row + g) * 132 + n] = tf32f(sc[nt][0] * inv0);
        Ps[(row + g) * 132 + n + 1] = tf32f(sc[nt][1] * inv0);
        Ps[(row + g + 8) * 132 + n] = tf32f(sc[nt][2] * inv1);
        Ps[(row + g + 8) * 132 + n + 1] = tf32f(sc[nt][3] * inv1);
    }
    __syncthreads();

    float oa[8][4];
#pragma unroll
    for (int nt = 0; nt < 8; nt++)
#pragma unroll
        for (int k = 0; k < 4; k++) oa[nt][k] = 0.f;
#pragma unroll
    for (int k0 = 0; k0 < 128; k0 += 8) {
        uint32_t a[4];
        a[0] = fu(Ps[(row + g) * 132 + k0 + qc]);
        a[1] = fu(Ps[(row + g + 8) * 132 + k0 + qc]);
        a[2] = fu(Ps[(row + g) * 132 + k0 + qc + 4]);
        a[3] = fu(Ps[(row + g + 8) * 132 + k0 + qc + 4]);
#pragma unroll
        for (int nt = 0; nt < 8; nt++) {
            uint32_t bb[2];
            bb[0] = fu(Vs[(k0 + qc) * 68 + nt * 8 + g]);
            bb[1] = fu(Vs[(k0 + qc + 4) * 68 + nt * 8 + g]);
            mma8(oa[nt], a, bb);
        }
    }
    __syncthreads();
    // stage row-attn out [l][d], stride 65
#pragma unroll
    for (int nt = 0; nt < 8; nt++) {
        int n = nt * 8 + 2 * qc;
        Os[(row + g) * 65 + n] = oa[nt][0];
        Os[(row + g) * 65 + n + 1] = oa[nt][1];
        Os[(row + g + 8) * 65 + n] = oa[nt][2];
        Os[(row + g + 8) * 65 + n + 1] = oa[nt][3];
    }
    __syncthreads();
    // add col-attn scratch (contiguous reads)
#pragma unroll
    for (int rep = 0; rep < 8; rep++) {
        int idx = rep * 256 + tid;
        int l = idx >> 4;
        int d4 = (idx & 15) * 4;
        float4 c4 = *reinterpret_cast<const float4*>(g_oc + rbase + (size_t)idx * 4);
        int so = l * 65 + d4;
        Os[so] += c4.x;
        Os[so + 1] += c4.y;
        Os[so + 2] += c4.z;
        Os[so + 3] += c4.w;
    }
    __syncthreads();
    // transposed, fully coalesced final write: out[b][h*64+d][s][l]
#pragma unroll
    for (int rep = 0; rep < 8; rep++) {
        int idx = rep * 256 + tid;           // 0..2047 = 64 d x 32 l4
        int d = idx >> 5;
        int l4 = (idx & 31) * 4;
        float4 v;
        v.x = Os[(l4 + 0) * 65 + d];
        v.y = Os[(l4 + 1) * 65 + d];
        v.z = Os[(l4 + 2) * 65 + d];
        v.w = Os[(l4 + 3) * 65 + d];
        size_t oaddr = (((size_t)(b * 512 + h * 64 + d)) * 128 + s) * 128 + l4;
        *reinterpret_cast<float4*>(out + oaddr) = v;
    }
}

extern "C" void kernel_launch(void* const* d_in, const int* in_sizes, int n_in,
                              void* d_out, int out_size) {
    const float* x = (const float*)d_in[0];
    const float* W = (const float*)d_in[1];
    const float* bias = (const float*)d_in[2];
    float* out = (float*)d_out;

    cudaFuncSetAttribute(k_qkv, cudaFuncAttributeMaxDynamicSharedMemorySize, K1_SMEM);
    cudaFuncSetAttribute(k_colattn, cudaFuncAttributeMaxDynamicSharedMemorySize, ATTN_SMEM);
    cudaFuncSetAttribute(k_rowattn, cudaFuncAttributeMaxDynamicSharedMemorySize, ATTN_SMEM);

    k_qkv<<<dim3(12, 128, 2), 256, K1_SMEM>>>(x, W, bias);
    k_colattn<<<dim3(128, 8, 2), 256, ATTN_SMEM>>>();
    k_rowattn<<<dim3(128, 8, 2), 256, ATTN_SMEM>>>(out);
}

// round 3
// speedup vs baseline: 1.0022x; 1.0022x over previous
#include <cuda_runtime.h>
#include <cstdint>

// Problem constants
// x: [B=2, E=512, S=128, L=128] fp32 ; W: [1536, 512] ; b: [1536]
// out: [2, 512, 128, 128] fp32
#define NB 2
#define NH 8
#define DH 64
#define NS 128
#define NL 128
// scratch layout: [b][h][s][l][d], d contiguous
#define QKV_ELEMS (NB * NH * NS * NL * DH)   // 16,777,216 floats = 64MB

__device__ __align__(256) float g_q[QKV_ELEMS];
__device__ __align__(256) float g_k[QKV_ELEMS];
__device__ __align__(256) float g_v[QKV_ELEMS];
__device__ __align__(256) float g_oc[QKV_ELEMS];

// ---------- helpers ----------
__device__ __forceinline__ uint32_t tf32u(float x) {
    uint32_t r;
    asm("cvt.rna.tf32.f32 %0, %1;" : "=r"(r) : "f"(x));
    return r;
}
__device__ __forceinline__ float tf32f(float x) { return __uint_as_float(tf32u(x)); }
__device__ __forceinline__ uint32_t fu(float x) { return __float_as_uint(x); }

__device__ __forceinline__ void mma8(float (&d)[4], const uint32_t (&a)[4], const uint32_t (&b)[2]) {
    asm volatile(
        "mma.sync.aligned.m16n8k8.row.col.f32.tf32.tf32.f32 "
        "{%0,%1,%2,%3}, {%4,%5,%6,%7}, {%8,%9}, {%0,%1,%2,%3};\n"
        : "+f"(d[0]), "+f"(d[1]), "+f"(d[2]), "+f"(d[3])
        : "r"(a[0]), "r"(a[1]), "r"(a[2]), "r"(a[3]), "r"(b[0]), "r"(b[1]));
}

// =====================================================================
// K1: QKV GEMM.  C[o, p] = sum_i W[o,i] * X[b][i][p] (+bias), p = s*128+l
// Block tile: 128 (o) x 128 (p=one s row, all l). K chunks of 32.
// Epilogue: transpose via smem, scatter to g_q/g_k/g_v [b][h][s][l][d].
// =====================================================================
#define K1_SMEM (128 * 129 * 4)   // Cs dominates (As+Bs = 2*32*132 floats fits under it)

__global__ void __launch_bounds__(256, 1) k_qkv(const float* __restrict__ X,
                                                const float* __restrict__ W,
                                                const float* __restrict__ bias) {
    extern __shared__ float sm[];
    float* As = sm;               // [32][132] k-major: As[k][m]
    float* Bs = sm + 32 * 132;    // [32][132]          Bs[k][n]
    const int tid = threadIdx.x;
    const int warp = tid >> 5, lane = tid & 31;
    const int g = lane >> 2, qc = lane & 3;
    const int wm = warp >> 2, wn = warp & 3;        // 2 x 4 warp grid
    const int o0 = blockIdx.x * 128;
    const int s = blockIdx.y;
    const int b = blockIdx.z;
    const float* Xb = X + (size_t)b * 512 * 16384 + (size_t)s * 128;

    float acc[4][4][4];
#pragma unroll
    for (int i = 0; i < 4; i++)
#pragma unroll
        for (int j = 0; j < 4; j++)
#pragma unroll
            for (int k = 0; k < 4; k++) acc[i][j][k] = 0.f;

    for (int kk = 0; kk < 512; kk += 32) {
        // Load W tile [128 o x 32 k] -> As[k][m], tf32-rounded
#pragma unroll
        for (int rep = 0; rep < 4; rep++) {
            int idx = rep * 256 + tid;        // 0..1023
            int r = idx >> 3;                 // 0..127 (o)
            int kq = (idx & 7) * 4;           // 0..28
            const float4 v = *reinterpret_cast<const float4*>(W + (size_t)(o0 + r) * 512 + kk + kq);
            As[(kq + 0) * 132 + r] = tf32f(v.x);
            As[(kq + 1) * 132 + r] = tf32f(v.y);
            As[(kq + 2) * 132 + r] = tf32f(v.z);
            As[(kq + 3) * 132 + r] = tf32f(v.w);
        }
        // Load X tile [32 k x 128 n] -> Bs[k][n]
#pragma unroll
        for (int rep = 0; rep < 4; rep++) {
            int idx = rep * 256 + tid;
            int r = idx >> 5;                 // 0..31 (k)
            int c4 = (idx & 31) * 4;          // 0..124
            const float4 v = *reinterpret_cast<const float4*>(Xb + (size_t)(kk + r) * 16384 + c4);
            float4 w4 = make_float4(tf32f(v.x), tf32f(v.y), tf32f(v.z), tf32f(v.w));
            *reinterpret_cast<float4*>(&Bs[r * 132 + c4]) = w4;
        }
        __syncthreads();
#pragma unroll
        for (int k0 = 0; k0 < 32; k0 += 8) {
            uint32_t af[4][4], bf[4][2];
#pragma unroll
            for (int mt = 0; mt < 4; mt++) {
                int m = wm * 64 + mt * 16 + g;
                af[mt][0] = fu(As[(k0 + qc) * 132 + m]);
                af[mt][1] = fu(As[(k0 + qc) * 132 + m + 8]);
                af[mt][2] = fu(As[(k0 + qc + 4) * 132 + m]);
                af[mt][3] = fu(As[(k0 + qc + 4) * 132 + m + 8]);
            }
#pragma unroll
            for (int nt = 0; nt < 4; nt++) {
                int n = wn * 32 + nt * 8 + g;
                bf[nt][0] = fu(Bs[(k0 + qc) * 132 + n]);
                bf[nt][1] = fu(Bs[(k0 + qc + 4) * 132 + n]);
            }
#pragma unroll
            for (int mt = 0; mt < 4; mt++)
#pragma unroll
                for (int nt = 0; nt < 4; nt++) mma8(acc[mt][nt], af[mt], bf[nt]);
        }
        __syncthreads();
    }

    // Stage C tile [128 o][128 l] into smem for transposed scatter
    float* Cs = sm;   // [128][129]
#pragma unroll
    for (int mt = 0; mt < 4; mt++)
#pragma unroll
        for (int nt = 0; nt < 4; nt++) {
            int r = wm * 64 + mt * 16 + g;
            int n = wn * 32 + nt * 8 + 2 * qc;
            Cs[r * 129 + n] = acc[mt][nt][0];
            Cs[r * 129 + n + 1] = acc[mt][nt][1];
            Cs[(r + 8) * 129 + n] = acc[mt][nt][2];
            Cs[(r + 8) * 129 + n + 1] = acc[mt][nt][3];
        }
    __syncthreads();

    const int sel = o0 >> 9;                 // 0=q 1=k 2=v
    const int h0 = (o0 & 511) >> 6;          // tile covers heads h0, h0+1
    float* dst = (sel == 0) ? g_q : ((sel == 1) ? g_k : g_v);
    const float scale = (sel == 0) ? 0.125f : 1.0f;   // DH^-0.5
#pragma unroll
    for (int rep = 0; rep < 16; rep++) {
        int idx = rep * 256 + tid;           // 0..4095 float4s
        int d4 = (idx & 15) * 4;             // 0..60
        int l = (idx >> 4) & 127;
        int hh = idx >> 11;                  // 0..1
        int od = hh * 64 + d4;
        float4 v;
        v.x = (Cs[(od + 0) * 129 + l] + bias[o0 + od + 0]) * scale;
        v.y = (Cs[(od + 1) * 129 + l] + bias[o0 + od + 1]) * scale;
        v.z = (Cs[(od + 2) * 129 + l] + bias[o0 + od + 2]) * scale;
        v.w = (Cs[(od + 3) * 129 + l] + bias[o0 + od + 3]) * scale;
        size_t da = (((size_t)((b * 8 + h0 + hh) * 128 + s)) * 128 + l) * 64 + d4;
        *reinterpret_cast<float4*>(dst + da) = v;
    }
}

// =====================================================================
// Attention core shared structure (written out twice):
// 128 (seq) x 128 (seq) x 64 (d) attention per CTA, 8 warps.
// Warp w owns score rows 16w..16w+15.
// =====================================================================
#define ATTN_SMEM ((3 * 128 * 68 + 128 * 132) * 4)   // 172,032 B

// K2: column attention. Block = (l, h, b). Writes g_oc[b][h][s][l][d].
__global__ void __launch_bounds__(256, 1) k_colattn() {
    extern __shared__ float sm[];
    float* Qs = sm;                   // [128][68]
    float* Ks = sm + 128 * 68;
    float* Vs = sm + 2 * 128 * 68;
    float* Ps = sm + 3 * 128 * 68;    // [128][132]
    float* Os = sm;                   // overlay on Qs: [128][68]
    const int tid = threadIdx.x;
    const int warp = tid >> 5, lane = tid & 31;
    const int g = lane >> 2, qc = lane & 3;
    const int l = blockIdx.x, h = blockIdx.y, b = blockIdx.z;
    const size_t base = (size_t)((b * 8 + h) * 128) * 8192;   // + s*8192 + l*64 + d

    // Gather Q,K,V tiles [s][d] for this column l (256B rows, coalesced)
#pragma unroll
    for (int rep = 0; rep < 8; rep++) {
        int idx = rep * 256 + tid;           // 0..2047
        int s = idx >> 4;
        int d4 = (idx & 15) * 4;
        size_t ga = base + (size_t)s * 8192 + (size_t)l * 64 + d4;
        float4 q4 = *reinterpret_cast<const float4*>(g_q + ga);
        float4 k4 = *reinterpret_cast<const float4*>(g_k + ga);
        float4 v4 = *reinterpret_cast<const float4*>(g_v + ga);
        int so = s * 68 + d4;
        *reinterpret_cast<float4*>(&Qs[so]) = make_float4(tf32f(q4.x), tf32f(q4.y), tf32f(q4.z), tf32f(q4.w));
        *reinterpret_cast<float4*>(&Ks[so]) = make_float4(tf32f(k4.x), tf32f(k4.y), tf32f(k4.z), tf32f(k4.w));
        *reinterpret_cast<float4*>(&Vs[so]) = make_float4(tf32f(v4.x), tf32f(v4.y), tf32f(v4.z), tf32f(v4.w));
    }
    __syncthreads();

    // scores[s][t] = sum_d Q[s][d] * K[t][d]
    float sc[16][4];
#pragma unroll
    for (int nt = 0; nt < 16; nt++)
#pragma unroll
        for (int k = 0; k < 4; k++) sc[nt][k] = 0.f;
    const int row = warp * 16;
#pragma unroll
    for (int k0 = 0; k0 < 64; k0 += 8) {
        uint32_t a[4];
        a[0] = fu(Qs[(row + g) * 68 + k0 + qc]);
        a[1] = fu(Qs[(row + g + 8) * 68 + k0 + qc]);
        a[2] = fu(Qs[(row + g) * 68 + k0 + qc + 4]);
        a[3] = fu(Qs[(row + g + 8) * 68 + k0 + qc + 4]);
#pragma unroll
        for (int nt = 0; nt < 16; nt++) {
            uint32_t bb[2];
            bb[0] = fu(Ks[(nt * 8 + g) * 68 + k0 + qc]);
            bb[1] = fu(Ks[(nt * 8 + g) * 68 + k0 + qc + 4]);
            mma8(sc[nt], a, bb);
        }
    }
    // softmax over t (each thread: rows {row+g, row+g+8}, 32 cols each)
    float m0 = -1e30f, m1 = -1e30f;
#pragma unroll
    for (int nt = 0; nt < 16; nt++) {
        m0 = fmaxf(m0, fmaxf(sc[nt][0], sc[nt][1]));
        m1 = fmaxf(m1, fmaxf(sc[nt][2], sc[nt][3]));
    }
    m0 = fmaxf(m0, __shfl_xor_sync(0xffffffffu, m0, 1));
    m0 = fmaxf(m0, __shfl_xor_sync(0xffffffffu, m0, 2));
    m1 = fmaxf(m1, __shfl_xor_sync(0xffffffffu, m1, 1));
    m1 = fmaxf(m1, __shfl_xor_sync(0xffffffffu, m1, 2));
    const float LOG2E = 1.4426950408889634f;
    float s0 = 0.f, s1 = 0.f;
#pragma unroll
    for (int nt = 0; nt < 16; nt++) {
        sc[nt][0] = exp2f((sc[nt][0] - m0) * LOG2E); s0 += sc[nt][0];
        sc[nt][1] = exp2f((sc[nt][1] - m0) * LOG2E); s0 += sc[nt][1];
        sc[nt][2] = exp2f((sc[nt][2] - m1) * LOG2E); s1 += sc[nt][2];
        sc[nt][3] = exp2f((sc[nt][3] - m1) * LOG2E); s1 += sc[nt][3];
    }
    s0 += __shfl_xor_sync(0xffffffffu, s0, 1);
    s0 += __shfl_xor_sync(0xffffffffu, s0, 2);
    s1 += __shfl_xor_sync(0xffffffffu, s1, 1);
    s1 += __shfl_xor_sync(0xffffffffu, s1, 2);
    const float inv0 = 1.0f / s0, inv1 = 1.0f / s1;
#pragma unroll
    for (int nt = 0; nt < 16; nt++) {
        int n = nt * 8 + 2 * qc;
        Ps[(row + g) * 132 + n] = tf32f(sc[nt][0] * inv0);
        Ps[(row + g) * 132 + n + 1] = tf32f(sc[nt][1] * inv0);
        Ps[(row + g + 8) * 132 + n] = tf32f(sc[nt][2] * inv1);
        Ps[(row + g + 8) * 132 + n + 1] = tf32f(sc[nt][3] * inv1);
    }
    __syncthreads();

    // out[s][d] = P[s][t] @ V[t][d]
    float oa[8][4];
#pragma unroll
    for (int nt = 0; nt < 8; nt++)
#pragma unroll
        for (int k = 0; k < 4; k++) oa[nt][k] = 0.f;
#pragma unroll
    for (int k0 = 0; k0 < 128; k0 += 8) {
        uint32_t a[4];
        a[0] = fu(Ps[(row + g) * 132 + k0 + qc]);
        a[1] = fu(Ps[(row + g + 8) * 132 + k0 + qc]);
        a[2] = fu(Ps[(row + g) * 132 + k0 + qc + 4]);
        a[3] = fu(Ps[(row + g + 8) * 132 + k0 + qc + 4]);
#pragma unroll
        for (int nt = 0; nt < 8; nt++) {
            uint32_t bb[2];
            bb[0] = fu(Vs[(k0 + qc) * 68 + nt * 8 + g]);
            bb[1] = fu(Vs[(k0 + qc + 4) * 68 + nt * 8 + g]);
            mma8(oa[nt], a, bb);
        }
    }
    __syncthreads();
#pragma unroll
    for (int nt = 0; nt < 8; nt++) {
        int n = nt * 8 + 2 * qc;
        Os[(row + g) * 68 + n] = oa[nt][0];
        Os[(row + g) * 68 + n + 1] = oa[nt][1];
        Os[(row + g + 8) * 68 + n] = oa[nt][2];
        Os[(row + g + 8) * 68 + n + 1] = oa[nt][3];
    }
    __syncthreads();
#pragma unroll
    for (int rep = 0; rep < 8; rep++) {
        int idx = rep * 256 + tid;
        int s = idx >> 4;
        int d4 = (idx & 15) * 4;
        float4 v = *reinterpret_cast<const float4*>(&Os[s * 68 + d4]);
        *reinterpret_cast<float4*>(g_oc + base + (size_t)s * 8192 + (size_t)l * 64 + d4) = v;
    }
}

// K3: row attention + add col result + write final output [B,512,S,L].
__global__ void __launch_bounds__(256, 1) k_rowattn(float* __restrict__ out) {
    extern __shared__ float sm[];
    float* Qs = sm;
    float* Ks = sm + 128 * 68;
    float* Vs = sm + 2 * 128 * 68;
    float* Ps = sm + 3 * 128 * 68;
    float* Os = sm;                  // [128][65] overlay
    const int tid = threadIdx.x;
    const int warp = tid >> 5, lane = tid & 31;
    const int g = lane >> 2, qc = lane & 3;
    const int s = blockIdx.x, h = blockIdx.y, b = blockIdx.z;
    const size_t rbase = (size_t)((b * 8 + h) * 128) * 8192 + (size_t)s * 8192;

    // Fully contiguous 32KB loads per tensor
#pragma unroll
    for (int rep = 0; rep < 8; rep++) {
        int idx = rep * 256 + tid;
        int l = idx >> 4;
        int d4 = (idx & 15) * 4;
        size_t ga = rbase + (size_t)idx * 4;
        float4 q4 = *reinterpret_cast<const float4*>(g_q + ga);
        float4 k4 = *reinterpret_cast<const float4*>(g_k + ga);
        float4 v4 = *reinterpret_cast<const float4*>(g_v + ga);
        int so = l * 68 + d4;
        *reinterpret_cast<float4*>(&Qs[so]) = make_float4(tf32f(q4.x), tf32f(q4.y), tf32f(q4.z), tf32f(q4.w));
        *reinterpret_cast<float4*>(&Ks[so]) = make_float4(tf32f(k4.x), tf32f(k4.y), tf32f(k4.z), tf32f(k4.w));
        *reinterpret_cast<float4*>(&Vs[so]) = make_float4(tf32f(v4.x), tf32f(v4.y), tf32f(v4.z), tf32f(v4.w));
    }
    __syncthreads();

    float sc[16][4];
#pragma unroll
    for (int nt = 0; nt < 16; nt++)
#pragma unroll
        for (int k = 0; k < 4; k++) sc[nt][k] = 0.f;
    const int row = warp * 16;
#pragma unroll
    for (int k0 = 0; k0 < 64; k0 += 8) {
        uint32_t a[4];
        a[0] = fu(Qs[(row + g) * 68 + k0 + qc]);
        a[1] = fu(Qs[(row + g + 8) * 68 + k0 + qc]);
        a[2] = fu(Qs[(row + g) * 68 + k0 + qc + 4]);
        a[3] = fu(Qs[(row + g + 8) * 68 + k0 + qc + 4]);
#pragma unroll
        for (int nt = 0; nt < 16; nt++) {
            uint32_t bb[2];
            bb[0] = fu(Ks[(nt * 8 + g) * 68 + k0 + qc]);
            bb[1] = fu(Ks[(nt * 8 + g) * 68 + k0 + qc + 4]);
            mma8(sc[nt], a, bb);
        }
    }
    float m0 = -1e30f, m1 = -1e30f;
#pragma unroll
    for (int nt = 0; nt < 16; nt++) {
        m0 = fmaxf(m0, fmaxf(sc[nt][0], sc[nt][1]));
        m1 = fmaxf(m1, fmaxf(sc[nt][2], sc[nt][3]));
    }
    m0 = fmaxf(m0, __shfl_xor_sync(0xffffffffu, m0, 1));
    m0 = fmaxf(m0, __shfl_xor_sync(0xffffffffu, m0, 2));
    m1 = fmaxf(m1, __shfl_xor_sync(0xffffffffu, m1, 1));
    m1 = fmaxf(m1, __shfl_xor_sync(0xffffffffu, m1, 2));
    const float LOG2E = 1.4426950408889634f;
    float s0 = 0.f, s1 = 0.f;
#pragma unroll
    for (int nt = 0; nt < 16; nt++) {
        sc[nt][0] = exp2f((sc[nt][0] - m0) * LOG2E); s0 += sc[nt][0];
        sc[nt][1] = exp2f((sc[nt][1] - m0) * LOG2E); s0 += sc[nt][1];
        sc[nt][2] = exp2f((sc[nt][2] - m1) * LOG2E); s1 += sc[nt][2];
        sc[nt][3] = exp2f((sc[nt][3] - m1) * LOG2E); s1 += sc[nt][3];
    }
    s0 += __shfl_xor_sync(0xffffffffu, s0, 1);
    s0 += __shfl_xor_sync(0xffffffffu, s0, 2);
    s1 += __shfl_xor_sync(0xffffffffu, s1, 1);
    s1 += __shfl_xor_sync(0xffffffffu, s1, 2);
    const float inv0 = 1.0f / s0, inv1 = 1.0f / s1;
#pragma unroll
    for (int nt = 0; nt < 16; nt++) {
        int n = nt * 8 + 2 * qc;
        Ps[(row + g) * 132 + n] = tf32f(sc[nt][0] * inv0);
        Ps[(row + g) * 132 + n + 1] = tf32f(sc[nt][1] * inv0);
        Ps[(row + g + 8) * 132 + n] = tf32f(sc[nt][2] * inv1);
        Ps[(row + g + 8) * 132 + n + 1] = tf32f(sc[nt][3] * inv1);
    }
    __syncthreads();

    float oa[8][4];
#pragma unroll
    for (int nt = 0; nt < 8; nt++)
#pragma unroll
        for (int k = 0; k < 4; k++) oa[nt][k] = 0.f;
#pragma unroll
    for (int k0 = 0; k0 < 128; k0 += 8) {
        uint32_t a[4];
        a[0] = fu(Ps[(row + g) * 132 + k0 + qc]);
        a[1] = fu(Ps[(row + g + 8) * 132 + k0 + qc]);
        a[2] = fu(Ps[(row + g) * 132 + k0 + qc + 4]);
        a[3] = fu(Ps[(row + g + 8) * 132 + k0 + qc + 4]);
#pragma unroll
        for (int nt = 0; nt < 8; nt++) {
            uint32_t bb[2];
            bb[0] = fu(Vs[(k0 + qc) * 68 + nt * 8 + g]);
            bb[1] = fu(Vs[(k0 + qc + 4) * 68 + nt * 8 + g]);
            mma8(oa[nt], a, bb);
        }
    }
    __syncthreads();
    // stage row-attn out [l][d], stride 65
#pragma unroll
    for (int nt = 0; nt < 8; nt++) {
        int n = nt * 8 + 2 * qc;
        Os[(row + g) * 65 + n] = oa[nt][0];
        Os[(row + g) * 65 + n + 1] = oa[nt][1];
        Os[(row + g + 8) * 65 + n] = oa[nt][2];
        Os[(row + g + 8) * 65 + n + 1] = oa[nt][3];
    }
    __syncthreads();
    // add col-attn scratch (contiguous reads)
#pragma unroll
    for (int rep = 0; rep < 8; rep++) {
        int idx = rep * 256 + tid;
        int l = idx >> 4;
        int d4 = (idx & 15) * 4;
        float4 c4 = *reinterpret_cast<const float4*>(g_oc + rbase + (size_t)idx * 4);
        int so = l * 65 + d4;
        Os[so] += c4.x;
        Os[so + 1] += c4.y;
        Os[so + 2] += c4.z;
        Os[so + 3] += c4.w;
    }
    __syncthreads();
    // transposed, fully coalesced final write: out[b][h*64+d][s][l]
#pragma unroll
    for (int rep = 0; rep < 8; rep++) {
        int idx = rep * 256 + tid;           // 0..2047 = 64 d x 32 l4
        int d = idx >> 5;
        int l4 = (idx & 31) * 4;
        float4 v;
        v.x = Os[(l4 + 0) * 65 + d];
        v.y = Os[(l4 + 1) * 65 + d];
        v.z = Os[(l4 + 2) * 65 + d];
        v.w = Os[(l4 + 3) * 65 + d];
        size_t oaddr = (((size_t)(b * 512 + h * 64 + d)) * 128 + s) * 128 + l4;
        *reinterpret_cast<float4*>(out + oaddr) = v;
    }
}

extern "C" void kernel_launch(void* const* d_in, const int* in_sizes, int n_in,
                              void* d_out, int out_size) {
    const float* x = (const float*)d_in[0];
    const float* W = (const float*)d_in[1];
    const float* bias = (const float*)d_in[2];
    float* out = (float*)d_out;

    cudaFuncSetAttribute(k_qkv, cudaFuncAttributeMaxDynamicSharedMemorySize, K1_SMEM);
    cudaFuncSetAttribute(k_colattn, cudaFuncAttributeMaxDynamicSharedMemorySize, ATTN_SMEM);
    cudaFuncSetAttribute(k_rowattn, cudaFuncAttributeMaxDynamicSharedMemorySize, ATTN_SMEM);

    k_qkv<<<dim3(12, 128, 2), 256, K1_SMEM>>>(x, W, bias);
    k_colattn<<<dim3(128, 8, 2), 256, ATTN_SMEM>>>();
    k_rowattn<<<dim3(128, 8, 2), 256, ATTN_SMEM>>>(out);
}

// round 4
// speedup vs baseline: 1.0067x; 1.0045x over previous
#include <cuda_runtime.h>
#include <cstdint>

// Problem constants
// x: [B=2, E=512, S=128, L=128] fp32 ; W: [1536, 512] ; b: [1536]
// out: [2, 512, 128, 128] fp32
#define NB 2
#define NH 8
#define DH 64
#define NS 128
#define NL 128
// scratch layout: [b][h][s][l][d], d contiguous
#define QKV_ELEMS (NB * NH * NS * NL * DH)   // 16,777,216 floats = 64MB

__device__ __align__(256) float g_q[QKV_ELEMS];
__device__ __align__(256) float g_k[QKV_ELEMS];
__device__ __align__(256) float g_v[QKV_ELEMS];
__device__ __align__(256) float g_oc[QKV_ELEMS];

// ---------- helpers ----------
__device__ __forceinline__ uint32_t tf32u(float x) {
    uint32_t r;
    asm("cvt.rna.tf32.f32 %0, %1;" : "=r"(r) : "f"(x));
    return r;
}
__device__ __forceinline__ float tf32f(float x) { return __uint_as_float(tf32u(x)); }
__device__ __forceinline__ uint32_t fu(float x) { return __float_as_uint(x); }

__device__ __forceinline__ void mma8(float (&d)[4], const uint32_t (&a)[4], const uint32_t (&b)[2]) {
    asm volatile(
        "mma.sync.aligned.m16n8k8.row.col.f32.tf32.tf32.f32 "
        "{%0,%1,%2,%3}, {%4,%5,%6,%7}, {%8,%9}, {%0,%1,%2,%3};\n"
        : "+f"(d[0]), "+f"(d[1]), "+f"(d[2]), "+f"(d[3])
        : "r"(a[0]), "r"(a[1]), "r"(a[2]), "r"(a[3]), "r"(b[0]), "r"(b[1]));
}

// =====================================================================
// K1: QKV GEMM.  C[o, p] = sum_i W[o,i] * X[b][i][p] (+bias), p = s*128+l
// Block tile: 128 (o) x 128 (p=one s row, all l). K chunks of 32.
// Epilogue: transpose via smem, scatter to g_q/g_k/g_v [b][h][s][l][d].
// =====================================================================
#define K1_SMEM (128 * 129 * 4)   // Cs dominates (As+Bs = 2*32*132 floats fits under it)

__global__ void __launch_bounds__(256, 1) k_qkv(const float* __restrict__ X,
                                                const float* __restrict__ W,
                                                const float* __restrict__ bias) {
    extern __shared__ float sm[];
    float* As = sm;               // [32][132] k-major: As[k][m]
    float* Bs = sm + 32 * 132;    // [32][132]          Bs[k][n]
    const int tid = threadIdx.x;
    const int warp = tid >> 5, lane = tid & 31;
    const int g = lane >> 2, qc = lane & 3;
    const int wm = warp >> 2, wn = warp & 3;        // 2 x 4 warp grid
    const int o0 = blockIdx.x * 128;
    const int s = blockIdx.y;
    const int b = blockIdx.z;
    const float* Xb = X + (size_t)b * 512 * 16384 + (size_t)s * 128;

    float acc[4][4][4];
#pragma unroll
    for (int i = 0; i < 4; i++)
#pragma unroll
        for (int j = 0; j < 4; j++)
#pragma unroll
            for (int k = 0; k < 4; k++) acc[i][j][k] = 0.f;

    for (int kk = 0; kk < 512; kk += 32) {
        // Load W tile [128 o x 32 k] -> As[k][m], tf32-rounded
#pragma unroll
        for (int rep = 0; rep < 4; rep++) {
            int idx = rep * 256 + tid;        // 0..1023
            int r = idx >> 3;                 // 0..127 (o)
            int kq = (idx & 7) * 4;           // 0..28
            const float4 v = *reinterpret_cast<const float4*>(W + (size_t)(o0 + r) * 512 + kk + kq);
            As[(kq + 0) * 132 + r] = tf32f(v.x);
            As[(kq + 1) * 132 + r] = tf32f(v.y);
            As[(kq + 2) * 132 + r] = tf32f(v.z);
            As[(kq + 3) * 132 + r] = tf32f(v.w);
        }
        // Load X tile [32 k x 128 n] -> Bs[k][n]
#pragma unroll
        for (int rep = 0; rep < 4; rep++) {
            int idx = rep * 256 + tid;
            int r = idx >> 5;                 // 0..31 (k)
            int c4 = (idx & 31) * 4;          // 0..124
            const float4 v = *reinterpret_cast<const float4*>(Xb + (size_t)(kk + r) * 16384 + c4);
            float4 w4 = make_float4(tf32f(v.x), tf32f(v.y), tf32f(v.z), tf32f(v.w));
            *reinterpret_cast<float4*>(&Bs[r * 132 + c4]) = w4;
        }
        __syncthreads();
#pragma unroll
        for (int k0 = 0; k0 < 32; k0 += 8) {
            uint32_t af[4][4], bf[4][2];
#pragma unroll
            for (int mt = 0; mt < 4; mt++) {
                int m = wm * 64 + mt * 16 + g;
                af[mt][0] = fu(As[(k0 + qc) * 132 + m]);
                af[mt][1] = fu(As[(k0 + qc) * 132 + m + 8]);
                af[mt][2] = fu(As[(k0 + qc + 4) * 132 + m]);
                af[mt][3] = fu(As[(k0 + qc + 4) * 132 + m + 8]);
            }
#pragma unroll
            for (int nt = 0; nt < 4; nt++) {
                int n = wn * 32 + nt * 8 + g;
                bf[nt][0] = fu(Bs[(k0 + qc) * 132 + n]);
                bf[nt][1] = fu(Bs[(k0 + qc + 4) * 132 + n]);
            }
#pragma unroll
            for (int mt = 0; mt < 4; mt++)
#pragma unroll
                for (int nt = 0; nt < 4; nt++) mma8(acc[mt][nt], af[mt], bf[nt]);
        }
        __syncthreads();
    }

    // Stage C tile [128 o][128 l] into smem for transposed scatter
    float* Cs = sm;   // [128][129]
#pragma unroll
    for (int mt = 0; mt < 4; mt++)
#pragma unroll
        for (int nt = 0; nt < 4; nt++) {
            int r = wm * 64 + mt * 16 + g;
            int n = wn * 32 + nt * 8 + 2 * qc;
            Cs[r * 129 + n] = acc[mt][nt][0];
            Cs[r * 129 + n + 1] = acc[mt][nt][1];
            Cs[(r + 8) * 129 + n] = acc[mt][nt][2];
            Cs[(r + 8) * 129 + n + 1] = acc[mt][nt][3];
        }
    __syncthreads();

    const int sel = o0 >> 9;                 // 0=q 1=k 2=v
    const int h0 = (o0 & 511) >> 6;          // tile covers heads h0, h0+1
    float* dst = (sel == 0) ? g_q : ((sel == 1) ? g_k : g_v);
    const float scale = (sel == 0) ? 0.125f : 1.0f;   // DH^-0.5
#pragma unroll
    for (int rep = 0; rep < 16; rep++) {
        int idx = rep * 256 + tid;           // 0..4095 float4s
        int d4 = (idx & 15) * 4;             // 0..60
        int l = (idx >> 4) & 127;
        int hh = idx >> 11;                  // 0..1
        int od = hh * 64 + d4;
        float4 v;
        v.x = (Cs[(od + 0) * 129 + l] + bias[o0 + od + 0]) * scale;
        v.y = (Cs[(od + 1) * 129 + l] + bias[o0 + od + 1]) * scale;
        v.z = (Cs[(od + 2) * 129 + l] + bias[o0 + od + 2]) * scale;
        v.w = (Cs[(od + 3) * 129 + l] + bias[o0 + od + 3]) * scale;
        size_t da = (((size_t)((b * 8 + h0 + hh) * 128 + s)) * 128 + l) * 64 + d4;
        *reinterpret_cast<float4*>(dst + da) = v;
    }
}

// =====================================================================
// Attention core shared structure (written out twice):
// 128 (seq) x 128 (seq) x 64 (d) attention per CTA, 8 warps.
// Warp w owns score rows 16w..16w+15.
// =====================================================================
#define ATTN_SMEM ((3 * 128 * 68 + 128 * 132) * 4)   // 172,032 B

// K2: column attention. Block = (l, h, b). Writes g_oc[b][h][s][l][d].
__global__ void __launch_bounds__(256, 1) k_colattn() {
    extern __shared__ float sm[];
    float* Qs = sm;                   // [128][68]
    float* Ks = sm + 128 * 68;
    float* Vs = sm + 2 * 128 * 68;
    float* Ps = sm + 3 * 128 * 68;    // [128][132]
    float* Os = sm;                   // overlay on Qs: [128][68]
    const int tid = threadIdx.x;
    const int warp = tid >> 5, lane = tid & 31;
    const int g = lane >> 2, qc = lane & 3;
    const int l = blockIdx.x, h = blockIdx.y, b = blockIdx.z;
    const size_t base = (size_t)((b * 8 + h) * 128) * 8192;   // + s*8192 + l*64 + d

    // Gather Q,K,V tiles [s][d] for this column l (256B rows, coalesced)
#pragma unroll
    for (int rep = 0; rep < 8; rep++) {
        int idx = rep * 256 + tid;           // 0..2047
        int s = idx >> 4;
        int d4 = (idx & 15) * 4;
        size_t ga = base + (size_t)s * 8192 + (size_t)l * 64 + d4;
        float4 q4 = *reinterpret_cast<const float4*>(g_q + ga);
        float4 k4 = *reinterpret_cast<const float4*>(g_k + ga);
        float4 v4 = *reinterpret_cast<const float4*>(g_v + ga);
        int so = s * 68 + d4;
        *reinterpret_cast<float4*>(&Qs[so]) = make_float4(tf32f(q4.x), tf32f(q4.y), tf32f(q4.z), tf32f(q4.w));
        *reinterpret_cast<float4*>(&Ks[so]) = make_float4(tf32f(k4.x), tf32f(k4.y), tf32f(k4.z), tf32f(k4.w));
        *reinterpret_cast<float4*>(&Vs[so]) = make_float4(tf32f(v4.x), tf32f(v4.y), tf32f(v4.z), tf32f(v4.w));
    }
    __syncthreads();

    // scores[s][t] = sum_d Q[s][d] * K[t][d]
    float sc[16][4];
#pragma unroll
    for (int nt = 0; nt < 16; nt++)
#pragma unroll
        for (int k = 0; k < 4; k++) sc[nt][k] = 0.f;
    const int row = warp * 16;
#pragma unroll
    for (int k0 = 0; k0 < 64; k0 += 8) {
        uint32_t a[4];
        a[0] = fu(Qs[(row + g) * 68 + k0 + qc]);
        a[1] = fu(Qs[(row + g + 8) * 68 + k0 + qc]);
        a[2] = fu(Qs[(row + g) * 68 + k0 + qc + 4]);
        a[3] = fu(Qs[(row + g + 8) * 68 + k0 + qc + 4]);
#pragma unroll
        for (int nt = 0; nt < 16; nt++) {
            uint32_t bb[2];
            bb[0] = fu(Ks[(nt * 8 + g) * 68 + k0 + qc]);
            bb[1] = fu(Ks[(nt * 8 + g) * 68 + k0 + qc + 4]);
            mma8(sc[nt], a, bb);
        }
    }
    // softmax over t (each thread: rows {row+g, row+g+8}, 32 cols each)
    float m0 = -1e30f, m1 = -1e30f;
#pragma unroll
    for (int nt = 0; nt < 16; nt++) {
        m0 = fmaxf(m0, fmaxf(sc[nt][0], sc[nt][1]));
        m1 = fmaxf(m1, fmaxf(sc[nt][2], sc[nt][3]));
    }
    m0 = fmaxf(m0, __shfl_xor_sync(0xffffffffu, m0, 1));
    m0 = fmaxf(m0, __shfl_xor_sync(0xffffffffu, m0, 2));
    m1 = fmaxf(m1, __shfl_xor_sync(0xffffffffu, m1, 1));
    m1 = fmaxf(m1, __shfl_xor_sync(0xffffffffu, m1, 2));
    const float LOG2E = 1.4426950408889634f;
    float s0 = 0.f, s1 = 0.f;
#pragma unroll
    for (int nt = 0; nt < 16; nt++) {
        sc[nt][0] = exp2f((sc[nt][0] - m0) * LOG2E); s0 += sc[nt][0];
        sc[nt][1] = exp2f((sc[nt][1] - m0) * LOG2E); s0 += sc[nt][1];
        sc[nt][2] = exp2f((sc[nt][2] - m1) * LOG2E); s1 += sc[nt][2];
        sc[nt][3] = exp2f((sc[nt][3] - m1) * LOG2E); s1 += sc[nt][3];
    }
    s0 += __shfl_xor_sync(0xffffffffu, s0, 1);
    s0 += __shfl_xor_sync(0xffffffffu, s0, 2);
    s1 += __shfl_xor_sync(0xffffffffu, s1, 1);
    s1 += __shfl_xor_sync(0xffffffffu, s1, 2);
    const float inv0 = 1.0f / s0, inv1 = 1.0f / s1;
#pragma unroll
    for (int nt = 0; nt < 16; nt++) {
        int n = nt * 8 + 2 * qc;
        Ps[(row + g) * 132 + n] = tf32f(sc[nt][0] * inv0);
        Ps[(row + g) * 132 + n + 1] = tf32f(sc[nt][1] * inv0);
        Ps[(row + g + 8) * 132 + n] = tf32f(sc[nt][2] * inv1);
        Ps[(row + g + 8) * 132 + n + 1] = tf32f(sc[nt][3] * inv1);
    }
    __syncthreads();

    // out[s][d] = P[s][t] @ V[t][d]
    float oa[8][4];
#pragma unroll
    for (int nt = 0; nt < 8; nt++)
#pragma unroll
        for (int k = 0; k < 4; k++) oa[nt][k] = 0.f;
#pragma unroll
    for (int k0 = 0; k0 < 128; k0 += 8) {
        uint32_t a[4];
        a[0] = fu(Ps[(row + g) * 132 + k0 + qc]);
        a[1] = fu(Ps[(row + g + 8) * 132 + k0 + qc]);
        a[2] = fu(Ps[(row + g) * 132 + k0 + qc + 4]);
        a[3] = fu(Ps[(row + g + 8) * 132 + k0 + qc + 4]);
#pragma unroll
        for (int nt = 0; nt < 8; nt++) {
            uint32_t bb[2];
            bb[0] = fu(Vs[(k0 + qc) * 68 + nt * 8 + g]);
            bb[1] = fu(Vs[(k0 + qc + 4) * 68 + nt * 8 + g]);
            mma8(oa[nt], a, bb);
        }
    }
    __syncthreads();
#pragma unroll
    for (int nt = 0; nt < 8; nt++) {
        int n = nt * 8 + 2 * qc;
        Os[(row + g) * 68 + n] = oa[nt][0];
        Os[(row + g) * 68 + n + 1] = oa[nt][1];
        Os[(row + g + 8) * 68 + n] = oa[nt][2];
        Os[(row + g + 8) * 68 + n + 1] = oa[nt][3];
    }
    __syncthreads();
#pragma unroll
    for (int rep = 0; rep < 8; rep++) {
        int idx = rep * 256 + tid;
        int s = idx >> 4;
        int d4 = (idx & 15) * 4;
        float4 v = *reinterpret_cast<const float4*>(&Os[s * 68 + d4]);
        *reinterpret_cast<float4*>(g_oc + base + (size_t)s * 8192 + (size_t)l * 64 + d4) = v;
    }
}

// K3: row attention + add col result + write final output [B,512,S,L].
__global__ void __launch_bounds__(256, 1) k_rowattn(float* __restrict__ out) {
    extern __shared__ float sm[];
    float* Qs = sm;
    float* Ks = sm + 128 * 68;
    float* Vs = sm + 2 * 128 * 68;
    float* Ps = sm + 3 * 128 * 68;
    float* Os = sm;                  // [128][65] overlay
    const int tid = threadIdx.x;
    const int warp = tid >> 5, lane = tid & 31;
    const int g = lane >> 2, qc = lane & 3;
    const int s = blockIdx.x, h = blockIdx.y, b = blockIdx.z;
    const size_t rbase = (size_t)((b * 8 + h) * 128) * 8192 + (size_t)s * 8192;

    // Fully contiguous 32KB loads per tensor
#pragma unroll
    for (int rep = 0; rep < 8; rep++) {
        int idx = rep * 256 + tid;
        int l = idx >> 4;
        int d4 = (idx & 15) * 4;
        size_t ga = rbase + (size_t)idx * 4;
        float4 q4 = *reinterpret_cast<const float4*>(g_q + ga);
        float4 k4 = *reinterpret_cast<const float4*>(g_k + ga);
        float4 v4 = *reinterpret_cast<const float4*>(g_v + ga);
        int so = l * 68 + d4;
        *reinterpret_cast<float4*>(&Qs[so]) = make_float4(tf32f(q4.x), tf32f(q4.y), tf32f(q4.z), tf32f(q4.w));
        *reinterpret_cast<float4*>(&Ks[so]) = make_float4(tf32f(k4.x), tf32f(k4.y), tf32f(k4.z), tf32f(k4.w));
        *reinterpret_cast<float4*>(&Vs[so]) = make_float4(tf32f(v4.x), tf32f(v4.y), tf32f(v4.z), tf32f(v4.w));
    }
    __syncthreads();

    float sc[16][4];
#pragma unroll
    for (int nt = 0; nt < 16; nt++)
#pragma unroll
        for (int k = 0; k < 4; k++) sc[nt][k] = 0.f;
    const int row = warp * 16;
#pragma unroll
    for (int k0 = 0; k0 < 64; k0 += 8) {
        uint32_t a[4];
        a[0] = fu(Qs[(row + g) * 68 + k0 + qc]);
        a[1] = fu(Qs[(row + g + 8) * 68 + k0 + qc]);
        a[2] = fu(Qs[(row + g) * 68 + k0 + qc + 4]);
        a[3] = fu(Qs[(row + g + 8) * 68 + k0 + qc + 4]);
#pragma unroll
        for (int nt = 0; nt < 16; nt++) {
            uint32_t bb[2];
            bb[0] = fu(Ks[(nt * 8 + g) * 68 + k0 + qc]);
            bb[1] = fu(Ks[(nt * 8 + g) * 68 + k0 + qc + 4]);
            mma8(sc[nt], a, bb);
        }
    }
    float m0 = -1e30f, m1 = -1e30f;
#pragma unroll
    for (int nt = 0; nt < 16; nt++) {
        m0 = fmaxf(m0, fmaxf(sc[nt][0], sc[nt][1]));
        m1 = fmaxf(m1, fmaxf(sc[nt][2], sc[nt][3]));
    }
    m0 = fmaxf(m0, __shfl_xor_sync(0xffffffffu, m0, 1));
    m0 = fmaxf(m0, __shfl_xor_sync(0xffffffffu, m0, 2));
    m1 = fmaxf(m1, __shfl_xor_sync(0xffffffffu, m1, 1));
    m1 = fmaxf(m1, __shfl_xor_sync(0xffffffffu, m1, 2));
    const float LOG2E = 1.4426950408889634f;
    float s0 = 0.f, s1 = 0.f;
#pragma unroll
    for (int nt = 0; nt < 16; nt++) {
        sc[nt][0] = exp2f((sc[nt][0] - m0) * LOG2E); s0 += sc[nt][0];
        sc[nt][1] = exp2f((sc[nt][1] - m0) * LOG2E); s0 += sc[nt][1];
        sc[nt][2] = exp2f((sc[nt][2] - m1) * LOG2E); s1 += sc[nt][2];
        sc[nt][3] = exp2f((sc[nt][3] - m1) * LOG2E); s1 += sc[nt][3];
    }
    s0 += __shfl_xor_sync(0xffffffffu, s0, 1);
    s0 += __shfl_xor_sync(0xffffffffu, s0, 2);
    s1 += __shfl_xor_sync(0xffffffffu, s1, 1);
    s1 += __shfl_xor_sync(0xffffffffu, s1, 2);
    const float inv0 = 1.0f / s0, inv1 = 1.0f / s1;
#pragma unroll
    for (int nt = 0; nt < 16; nt++) {
        int n = nt * 8 + 2 * qc;
        Ps[(row + g) * 132 + n] = tf32f(sc[nt][0] * inv0);
        Ps[(row + g) * 132 + n + 1] = tf32f(sc[nt][1] * inv0);
        Ps[(row + g + 8) * 132 + n] = tf32f(sc[nt][2] * inv1);
        Ps[(row + g + 8) * 132 + n + 1] = tf32f(sc[nt][3] * inv1);
    }
    __syncthreads();

    float oa[8][4];
#pragma unroll
    for (int nt = 0; nt < 8; nt++)
#pragma unroll
        for (int k = 0; k < 4; k++) oa[nt][k] = 0.f;
#pragma unroll
    for (int k0 = 0; k0 < 128; k0 += 8) {
        uint32_t a[4];
        a[0] = fu(Ps[(row + g) * 132 + k0 + qc]);
        a[1] = fu(Ps[(row + g + 8) * 132 + k0 + qc]);
        a[2] = fu(Ps[(row + g) * 132 + k0 + qc + 4]);
        a[3] = fu(Ps[(row + g + 8) * 132 + k0 + qc + 4]);
#pragma unroll
        for (int nt = 0; nt < 8; nt++) {
            uint32_t bb[2];
            bb[0] = fu(Vs[(k0 + qc) * 68 + nt * 8 + g]);
            bb[1] = fu(Vs[(k0 + qc + 4) * 68 + nt * 8 + g]);
            mma8(oa[nt], a, bb);
        }
    }
    __syncthreads();
    // stage row-attn out [l][d], stride 65
#pragma unroll
    for (int nt = 0; nt < 8; nt++) {
        int n = nt * 8 + 2 * qc;
        Os[(row + g) * 65 + n] = oa[nt][0];
        Os[(row + g) * 65 + n + 1] = oa[nt][1];
        Os[(row + g + 8) * 65 + n] = oa[nt][2];
        Os[(row + g + 8) * 65 + n + 1] = oa[nt][3];
    }
    __syncthreads();
    // add col-attn scratch (contiguous reads)
#pragma unroll
    for (int rep = 0; rep < 8; rep++) {
        int idx = rep * 256 + tid;
        int l = idx >> 4;
        int d4 = (idx & 15) * 4;
        float4 c4 = *reinterpret_cast<const float4*>(g_oc + rbase + (size_t)idx * 4);
        int so = l * 65 + d4;
        Os[so] += c4.x;
        Os[so + 1] += c4.y;
        Os[so + 2] += c4.z;
        Os[so + 3] += c4.w;
    }
    __syncthreads();
    // transposed, fully coalesced final write: out[b][h*64+d][s][l]
#pragma unroll
    for (int rep = 0; rep < 8; rep++) {
        int idx = rep * 256 + tid;           // 0..2047 = 64 d x 32 l4
        int d = idx >> 5;
        int l4 = (idx & 31) * 4;
        float4 v;
        v.x = Os[(l4 + 0) * 65 + d];
        v.y = Os[(l4 + 1) * 65 + d];
        v.z = Os[(l4 + 2) * 65 + d];
        v.w = Os[(l4 + 3) * 65 + d];
        size_t oaddr = (((size_t)(b * 512 + h * 64 + d)) * 128 + s) * 128 + l4;
        *reinterpret_cast<float4*>(out + oaddr) = v;
    }
}

extern "C" void kernel_launch(void* const* d_in, const int* in_sizes, int n_in,
                              void* d_out, int out_size) {
    const float* x = (const float*)d_in[0];
    const float* W = (const float*)d_in[1];
    const float* bias = (const float*)d_in[2];
    float* out = (float*)d_out;

    cudaFuncSetAttribute(k_qkv, cudaFuncAttributeMaxDynamicSharedMemorySize, K1_SMEM);
    cudaFuncSetAttribute(k_colattn, cudaFuncAttributeMaxDynamicSharedMemorySize, ATTN_SMEM);
    cudaFuncSetAttribute(k_rowattn, cudaFuncAttributeMaxDynamicSharedMemorySize, ATTN_SMEM);

    k_qkv<<<dim3(12, 128, 2), 256, K1_SMEM>>>(x, W, bias);
    k_colattn<<<dim3(128, 8, 2), 256, ATTN_SMEM>>>();
    k_rowattn<<<dim3(128, 8, 2), 256, ATTN_SMEM>>>(out);
}

// round 5
// speedup vs baseline: 1.0096x; 1.0028x over previous
#include <cuda_runtime.h>
#include <cstdint>

// Problem constants
// x: [B=2, E=512, S=128, L=128] fp32 ; W: [1536, 512] ; b: [1536]
// out: [2, 512, 128, 128] fp32
#define NB 2
#define NH 8
#define DH 64
#define NS 128
#define NL 128
// scratch layout: [b][h][s][l][d], d contiguous
#define QKV_ELEMS (NB * NH * NS * NL * DH)   // 16,777,216 floats = 64MB

__device__ __align__(256) float g_q[QKV_ELEMS];
__device__ __align__(256) float g_k[QKV_ELEMS];
__device__ __align__(256) float g_v[QKV_ELEMS];
__device__ __align__(256) float g_oc[QKV_ELEMS];

// ---------- helpers ----------
__device__ __forceinline__ uint32_t tf32u(float x) {
    uint32_t r;
    asm("cvt.rna.tf32.f32 %0, %1;" : "=r"(r) : "f"(x));
    return r;
}
__device__ __forceinline__ float tf32f(float x) { return __uint_as_float(tf32u(x)); }
__device__ __forceinline__ uint32_t fu(float x) { return __float_as_uint(x); }

__device__ __forceinline__ void mma8(float (&d)[4], const uint32_t (&a)[4], const uint32_t (&b)[2]) {
    asm volatile(
        "mma.sync.aligned.m16n8k8.row.col.f32.tf32.tf32.f32 "
        "{%0,%1,%2,%3}, {%4,%5,%6,%7}, {%8,%9}, {%0,%1,%2,%3};\n"
        : "+f"(d[0]), "+f"(d[1]), "+f"(d[2]), "+f"(d[3])
        : "r"(a[0]), "r"(a[1]), "r"(a[2]), "r"(a[3]), "r"(b[0]), "r"(b[1]));
}

// =====================================================================
// K1: QKV GEMM.  C[o, p] = sum_i W[o,i] * X[b][i][p] (+bias), p = s*128+l
// Block tile: 128 (o) x 128 (p=one s row, all l). K chunks of 32.
// Epilogue: transpose via smem, scatter to g_q/g_k/g_v [b][h][s][l][d].
// =====================================================================
#define K1_SMEM (128 * 129 * 4)   // Cs dominates (As+Bs = 2*32*132 floats fits under it)

__global__ void __launch_bounds__(256, 1) k_qkv(const float* __restrict__ X,
                                                const float* __restrict__ W,
                                                const float* __restrict__ bias) {
    extern __shared__ float sm[];
    float* As = sm;               // [32][132] k-major: As[k][m]
    float* Bs = sm + 32 * 132;    // [32][132]          Bs[k][n]
    const int tid = threadIdx.x;
    const int warp = tid >> 5, lane = tid & 31;
    const int g = lane >> 2, qc = lane & 3;
    const int wm = warp >> 2, wn = warp & 3;        // 2 x 4 warp grid
    const int o0 = blockIdx.x * 128;
    const int s = blockIdx.y;
    const int b = blockIdx.z;
    const float* Xb = X + (size_t)b * 512 * 16384 + (size_t)s * 128;

    float acc[4][4][4];
#pragma unroll
    for (int i = 0; i < 4; i++)
#pragma unroll
        for (int j = 0; j < 4; j++)
#pragma unroll
            for (int k = 0; k < 4; k++) acc[i][j][k] = 0.f;

    for (int kk = 0; kk < 512; kk += 32) {
        // Load W tile [128 o x 32 k] -> As[k][m], tf32-rounded
#pragma unroll
        for (int rep = 0; rep < 4; rep++) {
            int idx = rep * 256 + tid;        // 0..1023
            int r = idx >> 3;                 // 0..127 (o)
            int kq = (idx & 7) * 4;           // 0..28
            const float4 v = *reinterpret_cast<const float4*>(W + (size_t)(o0 + r) * 512 + kk + kq);
            As[(kq + 0) * 132 + r] = tf32f(v.x);
            As[(kq + 1) * 132 + r] = tf32f(v.y);
            As[(kq + 2) * 132 + r] = tf32f(v.z);
            As[(kq + 3) * 132 + r] = tf32f(v.w);
        }
        // Load X tile [32 k x 128 n] -> Bs[k][n]
#pragma unroll
        for (int rep = 0; rep < 4; rep++) {
            int idx = rep * 256 + tid;
            int r = idx >> 5;                 // 0..31 (k)
            int c4 = (idx & 31) * 4;          // 0..124
            const float4 v = *reinterpret_cast<const float4*>(Xb + (size_t)(kk + r) * 16384 + c4);
            float4 w4 = make_float4(tf32f(v.x), tf32f(v.y), tf32f(v.z), tf32f(v.w));
            *reinterpret_cast<float4*>(&Bs[r * 132 + c4]) = w4;
        }
        __syncthreads();
#pragma unroll
        for (int k0 = 0; k0 < 32; k0 += 8) {
            uint32_t af[4][4], bf[4][2];
#pragma unroll
            for (int mt = 0; mt < 4; mt++) {
                int m = wm * 64 + mt * 16 + g;
                af[mt][0] = fu(As[(k0 + qc) * 132 + m]);
                af[mt][1] = fu(As[(k0 + qc) * 132 + m + 8]);
                af[mt][2] = fu(As[(k0 + qc + 4) * 132 + m]);
                af[mt][3] = fu(As[(k0 + qc + 4) * 132 + m + 8]);
            }
#pragma unroll
            for (int nt = 0; nt < 4; nt++) {
                int n = wn * 32 + nt * 8 + g;
                bf[nt][0] = fu(Bs[(k0 + qc) * 132 + n]);
                bf[nt][1] = fu(Bs[(k0 + qc + 4) * 132 + n]);
            }
#pragma unroll
            for (int mt = 0; mt < 4; mt++)
#pragma unroll
                for (int nt = 0; nt < 4; nt++) mma8(acc[mt][nt], af[mt], bf[nt]);
        }
        __syncthreads();
    }

    // Stage C tile [128 o][128 l] into smem for transposed scatter
    float* Cs = sm;   // [128][129]
#pragma unroll
    for (int mt = 0; mt < 4; mt++)
#pragma unroll
        for (int nt = 0; nt < 4; nt++) {
            int r = wm * 64 + mt * 16 + g;
            int n = wn * 32 + nt * 8 + 2 * qc;
            Cs[r * 129 + n] = acc[mt][nt][0];
            Cs[r * 129 + n + 1] = acc[mt][nt][1];
            Cs[(r + 8) * 129 + n] = acc[mt][nt][2];
            Cs[(r + 8) * 129 + n + 1] = acc[mt][nt][3];
        }
    __syncthreads();

    const int sel = o0 >> 9;                 // 0=q 1=k 2=v
    const int h0 = (o0 & 511) >> 6;          // tile covers heads h0, h0+1
    float* dst = (sel == 0) ? g_q : ((sel == 1) ? g_k : g_v);
    const float scale = (sel == 0) ? 0.125f : 1.0f;   // DH^-0.5
#pragma unroll
    for (int rep = 0; rep < 16; rep++) {
        int idx = rep * 256 + tid;           // 0..4095 float4s
        int d4 = (idx & 15) * 4;             // 0..60
        int l = (idx >> 4) & 127;
        int hh = idx >> 11;                  // 0..1
        int od = hh * 64 + d4;
        float4 v;
        v.x = (Cs[(od + 0) * 129 + l] + bias[o0 + od + 0]) * scale;
        v.y = (Cs[(od + 1) * 129 + l] + bias[o0 + od + 1]) * scale;
        v.z = (Cs[(od + 2) * 129 + l] + bias[o0 + od + 2]) * scale;
        v.w = (Cs[(od + 3) * 129 + l] + bias[o0 + od + 3]) * scale;
        size_t da = (((size_t)((b * 8 + h0 + hh) * 128 + s)) * 128 + l) * 64 + d4;
        *reinterpret_cast<float4*>(dst + da) = v;
    }
}

// =====================================================================
// Attention core shared structure (written out twice):
// 128 (seq) x 128 (seq) x 64 (d) attention per CTA, 8 warps.
// Warp w owns score rows 16w..16w+15.
// =====================================================================
#define ATTN_SMEM ((3 * 128 * 68 + 128 * 132) * 4)   // 172,032 B

// K2: column attention. Block = (l, h, b). Writes g_oc[b][h][s][l][d].
__global__ void __launch_bounds__(256, 1) k_colattn() {
    extern __shared__ float sm[];
    float* Qs = sm;                   // [128][68]
    float* Ks = sm + 128 * 68;
    float* Vs = sm + 2 * 128 * 68;
    float* Ps = sm + 3 * 128 * 68;    // [128][132]
    float* Os = sm;                   // overlay on Qs: [128][68]
    const int tid = threadIdx.x;
    const int warp = tid >> 5, lane = tid & 31;
    const int g = lane >> 2, qc = lane & 3;
    const int l = blockIdx.x, h = blockIdx.y, b = blockIdx.z;
    const size_t base = (size_t)((b * 8 + h) * 128) * 8192;   // + s*8192 + l*64 + d

    // Gather Q,K,V tiles [s][d] for this column l (256B rows, coalesced)
#pragma unroll
    for (int rep = 0; rep < 8; rep++) {
        int idx = rep * 256 + tid;           // 0..2047
        int s = idx >> 4;
        int d4 = (idx & 15) * 4;
        size_t ga = base + (size_t)s * 8192 + (size_t)l * 64 + d4;
        float4 q4 = *reinterpret_cast<const float4*>(g_q + ga);
        float4 k4 = *reinterpret_cast<const float4*>(g_k + ga);
        float4 v4 = *reinterpret_cast<const float4*>(g_v + ga);
        int so = s * 68 + d4;
        *reinterpret_cast<float4*>(&Qs[so]) = make_float4(tf32f(q4.x), tf32f(q4.y), tf32f(q4.z), tf32f(q4.w));
        *reinterpret_cast<float4*>(&Ks[so]) = make_float4(tf32f(k4.x), tf32f(k4.y), tf32f(k4.z), tf32f(k4.w));
        *reinterpret_cast<float4*>(&Vs[so]) = make_float4(tf32f(v4.x), tf32f(v4.y), tf32f(v4.z), tf32f(v4.w));
    }
    __syncthreads();

    // scores[s][t] = sum_d Q[s][d] * K[t][d]
    float sc[16][4];
#pragma unroll
    for (int nt = 0; nt < 16; nt++)
#pragma unroll
        for (int k = 0; k < 4; k++) sc[nt][k] = 0.f;
    const int row = warp * 16;
#pragma unroll
    for (int k0 = 0; k0 < 64; k0 += 8) {
        uint32_t a[4];
        a[0] = fu(Qs[(row + g) * 68 + k0 + qc]);
        a[1] = fu(Qs[(row + g + 8) * 68 + k0 + qc]);
        a[2] = fu(Qs[(row + g) * 68 + k0 + qc + 4]);
        a[3] = fu(Qs[(row + g + 8) * 68 + k0 + qc + 4]);
#pragma unroll
        for (int nt = 0; nt < 16; nt++) {
            uint32_t bb[2];
            bb[0] = fu(Ks[(nt * 8 + g) * 68 + k0 + qc]);
            bb[1] = fu(Ks[(nt * 8 + g) * 68 + k0 + qc + 4]);
            mma8(sc[nt], a, bb);
        }
    }
    // softmax over t (each thread: rows {row+g, row+g+8}, 32 cols each)
    float m0 = -1e30f, m1 = -1e30f;
#pragma unroll
    for (int nt = 0; nt < 16; nt++) {
        m0 = fmaxf(m0, fmaxf(sc[nt][0], sc[nt][1]));
        m1 = fmaxf(m1, fmaxf(sc[nt][2], sc[nt][3]));
    }
    m0 = fmaxf(m0, __shfl_xor_sync(0xffffffffu, m0, 1));
    m0 = fmaxf(m0, __shfl_xor_sync(0xffffffffu, m0, 2));
    m1 = fmaxf(m1, __shfl_xor_sync(0xffffffffu, m1, 1));
    m1 = fmaxf(m1, __shfl_xor_sync(0xffffffffu, m1, 2));
    const float LOG2E = 1.4426950408889634f;
    float s0 = 0.f, s1 = 0.f;
#pragma unroll
    for (int nt = 0; nt < 16; nt++) {
        sc[nt][0] = exp2f((sc[nt][0] - m0) * LOG2E); s0 += sc[nt][0];
        sc[nt][1] = exp2f((sc[nt][1] - m0) * LOG2E); s0 += sc[nt][1];
        sc[nt][2] = exp2f((sc[nt][2] - m1) * LOG2E); s1 += sc[nt][2];
        sc[nt][3] = exp2f((sc[nt][3] - m1) * LOG2E); s1 += sc[nt][3];
    }
    s0 += __shfl_xor_sync(0xffffffffu, s0, 1);
    s0 += __shfl_xor_sync(0xffffffffu, s0, 2);
    s1 += __shfl_xor_sync(0xffffffffu, s1, 1);
    s1 += __shfl_xor_sync(0xffffffffu, s1, 2);
    const float inv0 = 1.0f / s0, inv1 = 1.0f / s1;
#pragma unroll
    for (int nt = 0; nt < 16; nt++) {
        int n = nt * 8 + 2 * qc;
        Ps[(row + g) * 132 + n] = tf32f(sc[nt][0] * inv0);
        Ps[(row + g) * 132 + n + 1] = tf32f(sc[nt][1] * inv0);
        Ps[(row + g + 8) * 132 + n] = tf32f(sc[nt][2] * inv1);
        Ps[(row + g + 8) * 132 + n + 1] = tf32f(sc[nt][3] * inv1);
    }
    __syncthreads();

    // out[s][d] = P[s][t] @ V[t][d]
    float oa[8][4];
#pragma unroll
    for (int nt = 0; nt < 8; nt++)
#pragma unroll
        for (int k = 0; k < 4; k++) oa[nt][k] = 0.f;
#pragma unroll
    for (int k0 = 0; k0 < 128; k0 += 8) {
        uint32_t a[4];
        a[0] = fu(Ps[(row + g) * 132 + k0 + qc]);
        a[1] = fu(Ps[(row + g + 8) * 132 + k0 + qc]);
        a[2] = fu(Ps[(row + g) * 132 + k0 + qc + 4]);
        a[3] = fu(Ps[(row + g + 8) * 132 + k0 + qc + 4]);
#pragma unroll
        for (int nt = 0; nt < 8; nt++) {
            uint32_t bb[2];
            bb[0] = fu(Vs[(k0 + qc) * 68 + nt * 8 + g]);
            bb[1] = fu(Vs[(k0 + qc + 4) * 68 + nt * 8 + g]);
            mma8(oa[nt], a, bb);
        }
    }
    __syncthreads();
#pragma unroll
    for (int nt = 0; nt < 8; nt++) {
        int n = nt * 8 + 2 * qc;
        Os[(row + g) * 68 + n] = oa[nt][0];
        Os[(row + g) * 68 + n + 1] = oa[nt][1];
        Os[(row + g + 8) * 68 + n] = oa[nt][2];
        Os[(row + g + 8) * 68 + n + 1] = oa[nt][3];
    }
    __syncthreads();
#pragma unroll
    for (int rep = 0; rep < 8; rep++) {
        int idx = rep * 256 + tid;
        int s = idx >> 4;
        int d4 = (idx & 15) * 4;
        float4 v = *reinterpret_cast<const float4*>(&Os[s * 68 + d4]);
        *reinterpret_cast<float4*>(g_oc + base + (size_t)s * 8192 + (size_t)l * 64 + d4) = v;
    }
}

// K3: row attention + add col result + write final output [B,512,S,L].
__global__ void __launch_bounds__(256, 1) k_rowattn(float* __restrict__ out) {
    extern __shared__ float sm[];
    float* Qs = sm;
    float* Ks = sm + 128 * 68;
    float* Vs = sm + 2 * 128 * 68;
    float* Ps = sm + 3 * 128 * 68;
    float* Os = sm;                  // [128][65] overlay
    const int tid = threadIdx.x;
    const int warp = tid >> 5, lane = tid & 31;
    const int g = lane >> 2, qc = lane & 3;
    const int s = blockIdx.x, h = blockIdx.y, b = blockIdx.z;
    const size_t rbase = (size_t)((b * 8 + h) * 128) * 8192 + (size_t)s * 8192;

    // Fully contiguous 32KB loads per tensor
#pragma unroll
    for (int rep = 0; rep < 8; rep++) {
        int idx = rep * 256 + tid;
        int l = idx >> 4;
        int d4 = (idx & 15) * 4;
        size_t ga = rbase + (size_t)idx * 4;
        float4 q4 = *reinterpret_cast<const float4*>(g_q + ga);
        float4 k4 = *reinterpret_cast<const float4*>(g_k + ga);
        float4 v4 = *reinterpret_cast<const float4*>(g_v + ga);
        int so = l * 68 + d4;
        *reinterpret_cast<float4*>(&Qs[so]) = make_float4(tf32f(q4.x), tf32f(q4.y), tf32f(q4.z), tf32f(q4.w));
        *reinterpret_cast<float4*>(&Ks[so]) = make_float4(tf32f(k4.x), tf32f(k4.y), tf32f(k4.z), tf32f(k4.w));
        *reinterpret_cast<float4*>(&Vs[so]) = make_float4(tf32f(v4.x), tf32f(v4.y), tf32f(v4.z), tf32f(v4.w));
    }
    __syncthreads();

    float sc[16][4];
#pragma unroll
    for (int nt = 0; nt < 16; nt++)
#pragma unroll
        for (int k = 0; k < 4; k++) sc[nt][k] = 0.f;
    const int row = warp * 16;
#pragma unroll
    for (int k0 = 0; k0 < 64; k0 += 8) {
        uint32_t a[4];
        a[0] = fu(Qs[(row + g) * 68 + k0 + qc]);
        a[1] = fu(Qs[(row + g + 8) * 68 + k0 + qc]);
        a[2] = fu(Qs[(row + g) * 68 + k0 + qc + 4]);
        a[3] = fu(Qs[(row + g + 8) * 68 + k0 + qc + 4]);
#pragma unroll
        for (int nt = 0; nt < 16; nt++) {
            uint32_t bb[2];
            bb[0] = fu(Ks[(nt * 8 + g) * 68 + k0 + qc]);
            bb[1] = fu(Ks[(nt * 8 + g) * 68 + k0 + qc + 4]);
            mma8(sc[nt], a, bb);
        }
    }
    float m0 = -1e30f, m1 = -1e30f;
#pragma unroll
    for (int nt = 0; nt < 16; nt++) {
        m0 = fmaxf(m0, fmaxf(sc[nt][0], sc[nt][1]));
        m1 = fmaxf(m1, fmaxf(sc[nt][2], sc[nt][3]));
    }
    m0 = fmaxf(m0, __shfl_xor_sync(0xffffffffu, m0, 1));
    m0 = fmaxf(m0, __shfl_xor_sync(0xffffffffu, m0, 2));
    m1 = fmaxf(m1, __shfl_xor_sync(0xffffffffu, m1, 1));
    m1 = fmaxf(m1, __shfl_xor_sync(0xffffffffu, m1, 2));
    const float LOG2E = 1.4426950408889634f;
    float s0 = 0.f, s1 = 0.f;
#pragma unroll
    for (int nt = 0; nt < 16; nt++) {
        sc[nt][0] = exp2f((sc[nt][0] - m0) * LOG2E); s0 += sc[nt][0];
        sc[nt][1] = exp2f((sc[nt][1] - m0) * LOG2E); s0 += sc[nt][1];
        sc[nt][2] = exp2f((sc[nt][2] - m1) * LOG2E); s1 += sc[nt][2];
        sc[nt][3] = exp2f((sc[nt][3] - m1) * LOG2E); s1 += sc[nt][3];
    }
    s0 += __shfl_xor_sync(0xffffffffu, s0, 1);
    s0 += __shfl_xor_sync(0xffffffffu, s0, 2);
    s1 += __shfl_xor_sync(0xffffffffu, s1, 1);
    s1 += __shfl_xor_sync(0xffffffffu, s1, 2);
    const float inv0 = 1.0f / s0, inv1 = 1.0f / s1;
#pragma unroll
    for (int nt = 0; nt < 16; nt++) {
        int n = nt * 8 + 2 * qc;
        Ps[(row + g) * 132 + n] = tf32f(sc[nt][0] * inv0);
        Ps[(row + g) * 132 + n + 1] = tf32f(sc[nt][1] * inv0);
        Ps[(row + g + 8) * 132 + n] = tf32f(sc[nt][2] * inv1);
        Ps[(row + g + 8) * 132 + n + 1] = tf32f(sc[nt][3] * inv1);
    }
    __syncthreads();

    float oa[8][4];
#pragma unroll
    for (int nt = 0; nt < 8; nt++)
#pragma unroll
        for (int k = 0; k < 4; k++) oa[nt][k] = 0.f;
#pragma unroll
    for (int k0 = 0; k0 < 128; k0 += 8) {
        uint32_t a[4];
        a[0] = fu(Ps[(row + g) * 132 + k0 + qc]);
        a[1] = fu(Ps[(row + g + 8) * 132 + k0 + qc]);
        a[2] = fu(Ps[(row + g) * 132 + k0 + qc + 4]);
        a[3] = fu(Ps[(row + g + 8) * 132 + k0 + qc + 4]);
#pragma unroll
        for (int nt = 0; nt < 8; nt++) {
            uint32_t bb[2];
            bb[0] = fu(Vs[(k0 + qc) * 68 + nt * 8 + g]);
            bb[1] = fu(Vs[(k0 + qc + 4) * 68 + nt * 8 + g]);
            mma8(oa[nt], a, bb);
        }
    }
    __syncthreads();
    // stage row-attn out [l][d], stride 65
#pragma unroll
    for (int nt = 0; nt < 8; nt++) {
        int n = nt * 8 + 2 * qc;
        Os[(row + g) * 65 + n] = oa[nt][0];
        Os[(row + g) * 65 + n + 1] = oa[nt][1];
        Os[(row + g + 8) * 65 + n] = oa[nt][2];
        Os[(row + g + 8) * 65 + n + 1] = oa[nt][3];
    }
    __syncthreads();
    // add col-attn scratch (contiguous reads)
#pragma unroll
    for (int rep = 0; rep < 8; rep++) {
        int idx = rep * 256 + tid;
        int l = idx >> 4;
        int d4 = (idx & 15) * 4;
        float4 c4 = *reinterpret_cast<const float4*>(g_oc + rbase + (size_t)idx * 4);
        int so = l * 65 + d4;
        Os[so] += c4.x;
        Os[so + 1] += c4.y;
        Os[so + 2] += c4.z;
        Os[so + 3] += c4.w;
    }
    __syncthreads();
    // transposed, fully coalesced final write: out[b][h*64+d][s][l]
#pragma unroll
    for (int rep = 0; rep < 8; rep++) {
        int idx = rep * 256 + tid;           // 0..2047 = 64 d x 32 l4
        int d = idx >> 5;
        int l4 = (idx & 31) * 4;
        float4 v;
        v.x = Os[(l4 + 0) * 65 + d];
        v.y = Os[(l4 + 1) * 65 + d];
        v.z = Os[(l4 + 2) * 65 + d];
        v.w = Os[(l4 + 3) * 65 + d];
        size_t oaddr = (((size_t)(b * 512 + h * 64 + d)) * 128 + s) * 128 + l4;
        *reinterpret_cast<float4*>(out + oaddr) = v;
    }
}

extern "C" void kernel_launch(void* const* d_in, const int* in_sizes, int n_in,
                              void* d_out, int out_size) {
    const float* x = (const float*)d_in[0];
    const float* W = (const float*)d_in[1];
    const float* bias = (const float*)d_in[2];
    float* out = (float*)d_out;

    cudaFuncSetAttribute(k_qkv, cudaFuncAttributeMaxDynamicSharedMemorySize, K1_SMEM);
    cudaFuncSetAttribute(k_colattn, cudaFuncAttributeMaxDynamicSharedMemorySize, ATTN_SMEM);
    cudaFuncSetAttribute(k_rowattn, cudaFuncAttributeMaxDynamicSharedMemorySize, ATTN_SMEM);

    k_qkv<<<dim3(12, 128, 2), 256, K1_SMEM>>>(x, W, bias);
    k_colattn<<<dim3(128, 8, 2), 256, ATTN_SMEM>>>();
    k_rowattn<<<dim3(128, 8, 2), 256, ATTN_SMEM>>>(out);
}

// round 6
// speedup vs baseline: 1.0119x; 1.0023x over previous
#include <cuda_runtime.h>
#include <cstdint>

// Problem constants
// x: [B=2, E=512, S=128, L=128] fp32 ; W: [1536, 512] ; b: [1536]
// out: [2, 512, 128, 128] fp32
#define NB 2
#define NH 8
#define DH 64
#define NS 128
#define NL 128
// scratch layout: [b][h][s][l][d], d contiguous
#define QKV_ELEMS (NB * NH * NS * NL * DH)   // 16,777,216 floats = 64MB

__device__ __align__(256) float g_q[QKV_ELEMS];
__device__ __align__(256) float g_k[QKV_ELEMS];
__device__ __align__(256) float g_v[QKV_ELEMS];
__device__ __align__(256) float g_oc[QKV_ELEMS];

// ---------- helpers ----------
__device__ __forceinline__ uint32_t tf32u(float x) {
    uint32_t r;
    asm("cvt.rna.tf32.f32 %0, %1;" : "=r"(r) : "f"(x));
    return r;
}
__device__ __forceinline__ float tf32f(float x) { return __uint_as_float(tf32u(x)); }
__device__ __forceinline__ uint32_t fu(float x) { return __float_as_uint(x); }

__device__ __forceinline__ void mma8(float (&d)[4], const uint32_t (&a)[4], const uint32_t (&b)[2]) {
    asm volatile(
        "mma.sync.aligned.m16n8k8.row.col.f32.tf32.tf32.f32 "
        "{%0,%1,%2,%3}, {%4,%5,%6,%7}, {%8,%9}, {%0,%1,%2,%3};\n"
        : "+f"(d[0]), "+f"(d[1]), "+f"(d[2]), "+f"(d[3])
        : "r"(a[0]), "r"(a[1]), "r"(a[2]), "r"(a[3]), "r"(b[0]), "r"(b[1]));
}

// =====================================================================
// K1: QKV GEMM.  C[o, p] = sum_i W[o,i] * X[b][i][p] (+bias), p = s*128+l
// Block tile: 128 (o) x 128 (p=one s row, all l). K chunks of 32.
// Epilogue: transpose via smem, scatter to g_q/g_k/g_v [b][h][s][l][d].
// =====================================================================
#define K1_SMEM (128 * 129 * 4)   // Cs dominates (As+Bs = 2*32*132 floats fits under it)

__global__ void __launch_bounds__(256, 1) k_qkv(const float* __restrict__ X,
                                                const float* __restrict__ W,
                                                const float* __restrict__ bias) {
    extern __shared__ float sm[];
    float* As = sm;               // [32][132] k-major: As[k][m]
    float* Bs = sm + 32 * 132;    // [32][132]          Bs[k][n]
    const int tid = threadIdx.x;
    const int warp = tid >> 5, lane = tid & 31;
    const int g = lane >> 2, qc = lane & 3;
    const int wm = warp >> 2, wn = warp & 3;        // 2 x 4 warp grid
    const int o0 = blockIdx.x * 128;
    const int s = blockIdx.y;
    const int b = blockIdx.z;
    const float* Xb = X + (size_t)b * 512 * 16384 + (size_t)s * 128;

    float acc[4][4][4];
#pragma unroll
    for (int i = 0; i < 4; i++)
#pragma unroll
        for (int j = 0; j < 4; j++)
#pragma unroll
            for (int k = 0; k < 4; k++) acc[i][j][k] = 0.f;

    for (int kk = 0; kk < 512; kk += 32) {
        // Load W tile [128 o x 32 k] -> As[k][m], tf32-rounded
#pragma unroll
        for (int rep = 0; rep < 4; rep++) {
            int idx = rep * 256 + tid;        // 0..1023
            int r = idx >> 3;                 // 0..127 (o)
            int kq = (idx & 7) * 4;           // 0..28
            const float4 v = *reinterpret_cast<const float4*>(W + (size_t)(o0 + r) * 512 + kk + kq);
            As[(kq + 0) * 132 + r] = tf32f(v.x);
            As[(kq + 1) * 132 + r] = tf32f(v.y);
            As[(kq + 2) * 132 + r] = tf32f(v.z);
            As[(kq + 3) * 132 + r] = tf32f(v.w);
        }
        // Load X tile [32 k x 128 n] -> Bs[k][n]
#pragma unroll
        for (int rep = 0; rep < 4; rep++) {
            int idx = rep * 256 + tid;
            int r = idx >> 5;                 // 0..31 (k)
            int c4 = (idx & 31) * 4;          // 0..124
            const float4 v = *reinterpret_cast<const float4*>(Xb + (size_t)(kk + r) * 16384 + c4);
            float4 w4 = make_float4(tf32f(v.x), tf32f(v.y), tf32f(v.z), tf32f(v.w));
            *reinterpret_cast<float4*>(&Bs[r * 132 + c4]) = w4;
        }
        __syncthreads();
#pragma unroll
        for (int k0 = 0; k0 < 32; k0 += 8) {
            uint32_t af[4][4], bf[4][2];
#pragma unroll
            for (int mt = 0; mt < 4; mt++) {
                int m = wm * 64 + mt * 16 + g;
                af[mt][0] = fu(As[(k0 + qc) * 132 + m]);
                af[mt][1] = fu(As[(k0 + qc) * 132 + m + 8]);
                af[mt][2] = fu(As[(k0 + qc + 4) * 132 + m]);
                af[mt][3] = fu(As[(k0 + qc + 4) * 132 + m + 8]);
            }
#pragma unroll
            for (int nt = 0; nt < 4; nt++) {
                int n = wn * 32 + nt * 8 + g;
                bf[nt][0] = fu(Bs[(k0 + qc) * 132 + n]);
                bf[nt][1] = fu(Bs[(k0 + qc + 4) * 132 + n]);
            }
#pragma unroll
            for (int mt = 0; mt < 4; mt++)
#pragma unroll
                for (int nt = 0; nt < 4; nt++) mma8(acc[mt][nt], af[mt], bf[nt]);
        }
        __syncthreads();
    }

    // Stage C tile [128 o][128 l] into smem for transposed scatter
    float* Cs = sm;   // [128][129]
#pragma unroll
    for (int mt = 0; mt < 4; mt++)
#pragma unroll
        for (int nt = 0; nt < 4; nt++) {
            int r = wm * 64 + mt * 16 + g;
            int n = wn * 32 + nt * 8 + 2 * qc;
            Cs[r * 129 + n] = acc[mt][nt][0];
            Cs[r * 129 + n + 1] = acc[mt][nt][1];
            Cs[(r + 8) * 129 + n] = acc[mt][nt][2];
            Cs[(r + 8) * 129 + n + 1] = acc[mt][nt][3];
        }
    __syncthreads();

    const int sel = o0 >> 9;                 // 0=q 1=k 2=v
    const int h0 = (o0 & 511) >> 6;          // tile covers heads h0, h0+1
    float* dst = (sel == 0) ? g_q : ((sel == 1) ? g_k : g_v);
    const float scale = (sel == 0) ? 0.125f : 1.0f;   // DH^-0.5
#pragma unroll
    for (int rep = 0; rep < 16; rep++) {
        int idx = rep * 256 + tid;           // 0..4095 float4s
        int d4 = (idx & 15) * 4;             // 0..60
        int l = (idx >> 4) & 127;
        int hh = idx >> 11;                  // 0..1
        int od = hh * 64 + d4;
        float4 v;
        v.x = (Cs[(od + 0) * 129 + l] + bias[o0 + od + 0]) * scale;
        v.y = (Cs[(od + 1) * 129 + l] + bias[o0 + od + 1]) * scale;
        v.z = (Cs[(od + 2) * 129 + l] + bias[o0 + od + 2]) * scale;
        v.w = (Cs[(od + 3) * 129 + l] + bias[o0 + od + 3]) * scale;
        size_t da = (((size_t)((b * 8 + h0 + hh) * 128 + s)) * 128 + l) * 64 + d4;
        *reinterpret_cast<float4*>(dst + da) = v;
    }
}

// =====================================================================
// Attention core shared structure (written out twice):
// 128 (seq) x 128 (seq) x 64 (d) attention per CTA, 8 warps.
// Warp w owns score rows 16w..16w+15.
// =====================================================================
#define ATTN_SMEM ((3 * 128 * 68 + 128 * 132) * 4)   // 172,032 B

// K2: column attention. Block = (l, h, b). Writes g_oc[b][h][s][l][d].
__global__ void __launch_bounds__(256, 1) k_colattn() {
    extern __shared__ float sm[];
    float* Qs = sm;                   // [128][68]
    float* Ks = sm + 128 * 68;
    float* Vs = sm + 2 * 128 * 68;
    float* Ps = sm + 3 * 128 * 68;    // [128][132]
    float* Os = sm;                   // overlay on Qs: [128][68]
    const int tid = threadIdx.x;
    const int warp = tid >> 5, lane = tid & 31;
    const int g = lane >> 2, qc = lane & 3;
    const int l = blockIdx.x, h = blockIdx.y, b = blockIdx.z;
    const size_t base = (size_t)((b * 8 + h) * 128) * 8192;   // + s*8192 + l*64 + d

    // Gather Q,K,V tiles [s][d] for this column l (256B rows, coalesced)
#pragma unroll
    for (int rep = 0; rep < 8; rep++) {
        int idx = rep * 256 + tid;           // 0..2047
        int s = idx >> 4;
        int d4 = (idx & 15) * 4;
        size_t ga = base + (size_t)s * 8192 + (size_t)l * 64 + d4;
        float4 q4 = *reinterpret_cast<const float4*>(g_q + ga);
        float4 k4 = *reinterpret_cast<const float4*>(g_k + ga);
        float4 v4 = *reinterpret_cast<const float4*>(g_v + ga);
        int so = s * 68 + d4;
        *reinterpret_cast<float4*>(&Qs[so]) = make_float4(tf32f(q4.x), tf32f(q4.y), tf32f(q4.z), tf32f(q4.w));
        *reinterpret_cast<float4*>(&Ks[so]) = make_float4(tf32f(k4.x), tf32f(k4.y), tf32f(k4.z), tf32f(k4.w));
        *reinterpret_cast<float4*>(&Vs[so]) = make_float4(tf32f(v4.x), tf32f(v4.y), tf32f(v4.z), tf32f(v4.w));
    }
    __syncthreads();

    // scores[s][t] = sum_d Q[s][d] * K[t][d]
    float sc[16][4];
#pragma unroll
    for (int nt = 0; nt < 16; nt++)
#pragma unroll
        for (int k = 0; k < 4; k++) sc[nt][k] = 0.f;
    const int row = warp * 16;
#pragma unroll
    for (int k0 = 0; k0 < 64; k0 += 8) {
        uint32_t a[4];
        a[0] = fu(Qs[(row + g) * 68 + k0 + qc]);
        a[1] = fu(Qs[(row + g + 8) * 68 + k0 + qc]);
        a[2] = fu(Qs[(row + g) * 68 + k0 + qc + 4]);
        a[3] = fu(Qs[(row + g + 8) * 68 + k0 + qc + 4]);
#pragma unroll
        for (int nt = 0; nt < 16; nt++) {
            uint32_t bb[2];
            bb[0] = fu(Ks[(nt * 8 + g) * 68 + k0 + qc]);
            bb[1] = fu(Ks[(nt * 8 + g) * 68 + k0 + qc + 4]);
            mma8(sc[nt], a, bb);
        }
    }
    // softmax over t (each thread: rows {row+g, row+g+8}, 32 cols each)
    float m0 = -1e30f, m1 = -1e30f;
#pragma unroll
    for (int nt = 0; nt < 16; nt++) {
        m0 = fmaxf(m0, fmaxf(sc[nt][0], sc[nt][1]));
        m1 = fmaxf(m1, fmaxf(sc[nt][2], sc[nt][3]));
    }
    m0 = fmaxf(m0, __shfl_xor_sync(0xffffffffu, m0, 1));
    m0 = fmaxf(m0, __shfl_xor_sync(0xffffffffu, m0, 2));
    m1 = fmaxf(m1, __shfl_xor_sync(0xffffffffu, m1, 1));
    m1 = fmaxf(m1, __shfl_xor_sync(0xffffffffu, m1, 2));
    const float LOG2E = 1.4426950408889634f;
    float s0 = 0.f, s1 = 0.f;
#pragma unroll
    for (int nt = 0; nt < 16; nt++) {
        sc[nt][0] = exp2f((sc[nt][0] - m0) * LOG2E); s0 += sc[nt][0];
        sc[nt][1] = exp2f((sc[nt][1] - m0) * LOG2E); s0 += sc[nt][1];
        sc[nt][2] = exp2f((sc[nt][2] - m1) * LOG2E); s1 += sc[nt][2];
        sc[nt][3] = exp2f((sc[nt][3] - m1) * LOG2E); s1 += sc[nt][3];
    }
    s0 += __shfl_xor_sync(0xffffffffu, s0, 1);
    s0 += __shfl_xor_sync(0xffffffffu, s0, 2);
    s1 += __shfl_xor_sync(0xffffffffu, s1, 1);
    s1 += __shfl_xor_sync(0xffffffffu, s1, 2);
    const float inv0 = 1.0f / s0, inv1 = 1.0f / s1;
#pragma unroll
    for (int nt = 0; nt < 16; nt++) {
        int n = nt * 8 + 2 * qc;
        Ps[(row + g) * 132 + n] = tf32f(sc[nt][0] * inv0);
        Ps[(row + g) * 132 + n + 1] = tf32f(sc[nt][1] * inv0);
        Ps[(row + g + 8) * 132 + n] = tf32f(sc[nt][2] * inv1);
        Ps[(row + g + 8) * 132 + n + 1] = tf32f(sc[nt][3] * inv1);
    }
    __syncthreads();

    // out[s][d] = P[s][t] @ V[t][d]
    float oa[8][4];
#pragma unroll
    for (int nt = 0; nt < 8; nt++)
#pragma unroll
        for (int k = 0; k < 4; k++) oa[nt][k] = 0.f;
#pragma unroll
    for (int k0 = 0; k0 < 128; k0 += 8) {
        uint32_t a[4];
        a[0] = fu(Ps[(row + g) * 132 + k0 + qc]);
        a[1] = fu(Ps[(row + g + 8) * 132 + k0 + qc]);
        a[2] = fu(Ps[(row + g) * 132 + k0 + qc + 4]);
        a[3] = fu(Ps[(row + g + 8) * 132 + k0 + qc + 4]);
#pragma unroll
        for (int nt = 0; nt < 8; nt++) {
            uint32_t bb[2];
            bb[0] = fu(Vs[(k0 + qc) * 68 + nt * 8 + g]);
            bb[1] = fu(Vs[(k0 + qc + 4) * 68 + nt * 8 + g]);
            mma8(oa[nt], a, bb);
        }
    }
    __syncthreads();
#pragma unroll
    for (int nt = 0; nt < 8; nt++) {
        int n = nt * 8 + 2 * qc;
        Os[(row + g) * 68 + n] = oa[nt][0];
        Os[(row + g) * 68 + n + 1] = oa[nt][1];
        Os[(row + g + 8) * 68 + n] = oa[nt][2];
        Os[(row + g + 8) * 68 + n + 1] = oa[nt][3];
    }
    __syncthreads();
#pragma unroll
    for (int rep = 0; rep < 8; rep++) {
        int idx = rep * 256 + tid;
        int s = idx >> 4;
        int d4 = (idx & 15) * 4;
        float4 v = *reinterpret_cast<const float4*>(&Os[s * 68 + d4]);
        *reinterpret_cast<float4*>(g_oc + base + (size_t)s * 8192 + (size_t)l * 64 + d4) = v;
    }
}

// K3: row attention + add col result + write final output [B,512,S,L].
__global__ void __launch_bounds__(256, 1) k_rowattn(float* __restrict__ out) {
    extern __shared__ float sm[];
    float* Qs = sm;
    float* Ks = sm + 128 * 68;
    float* Vs = sm + 2 * 128 * 68;
    float* Ps = sm + 3 * 128 * 68;
    float* Os = sm;                  // [128][65] overlay
    const int tid = threadIdx.x;
    const int warp = tid >> 5, lane = tid & 31;
    const int g = lane >> 2, qc = lane & 3;
    const int s = blockIdx.x, h = blockIdx.y, b = blockIdx.z;
    const size_t rbase = (size_t)((b * 8 + h) * 128) * 8192 + (size_t)s * 8192;

    // Fully contiguous 32KB loads per tensor
#pragma unroll
    for (int rep = 0; rep < 8; rep++) {
        int idx = rep * 256 + tid;
        int l = idx >> 4;
        int d4 = (idx & 15) * 4;
        size_t ga = rbase + (size_t)idx * 4;
        float4 q4 = *reinterpret_cast<const float4*>(g_q + ga);
        float4 k4 = *reinterpret_cast<const float4*>(g_k + ga);
        float4 v4 = *reinterpret_cast<const float4*>(g_v + ga);
        int so = l * 68 + d4;
        *reinterpret_cast<float4*>(&Qs[so]) = make_float4(tf32f(q4.x), tf32f(q4.y), tf32f(q4.z), tf32f(q4.w));
        *reinterpret_cast<float4*>(&Ks[so]) = make_float4(tf32f(k4.x), tf32f(k4.y), tf32f(k4.z), tf32f(k4.w));
        *reinterpret_cast<float4*>(&Vs[so]) = make_float4(tf32f(v4.x), tf32f(v4.y), tf32f(v4.z), tf32f(v4.w));
    }
    __syncthreads();

    float sc[16][4];
#pragma unroll
    for (int nt = 0; nt < 16; nt++)
#pragma unroll
        for (int k = 0; k < 4; k++) sc[nt][k] = 0.f;
    const int row = warp * 16;
#pragma unroll
    for (int k0 = 0; k0 < 64; k0 += 8) {
        uint32_t a[4];
        a[0] = fu(Qs[(row + g) * 68 + k0 + qc]);
        a[1] = fu(Qs[(row + g + 8) * 68 + k0 + qc]);
        a[2] = fu(Qs[(row + g) * 68 + k0 + qc + 4]);
        a[3] = fu(Qs[(row + g + 8) * 68 + k0 + qc + 4]);
#pragma unroll
        for (int nt = 0; nt < 16; nt++) {
            uint32_t bb[2];
            bb[0] = fu(Ks[(nt * 8 + g) * 68 + k0 + qc]);
            bb[1] = fu(Ks[(nt * 8 + g) * 68 + k0 + qc + 4]);
            mma8(sc[nt], a, bb);
        }
    }
    float m0 = -1e30f, m1 = -1e30f;
#pragma unroll
    for (int nt = 0; nt < 16; nt++) {
        m0 = fmaxf(m0, fmaxf(sc[nt][0], sc[nt][1]));
        m1 = fmaxf(m1, fmaxf(sc[nt][2], sc[nt][3]));
    }
    m0 = fmaxf(m0, __shfl_xor_sync(0xffffffffu, m0, 1));
    m0 = fmaxf(m0, __shfl_xor_sync(0xffffffffu, m0, 2));
    m1 = fmaxf(m1, __shfl_xor_sync(0xffffffffu, m1, 1));
    m1 = fmaxf(m1, __shfl_xor_sync(0xffffffffu, m1, 2));
    const float LOG2E = 1.4426950408889634f;
    float s0 = 0.f, s1 = 0.f;
#pragma unroll
    for (int nt = 0; nt < 16; nt++) {
        sc[nt][0] = exp2f((sc[nt][0] - m0) * LOG2E); s0 += sc[nt][0];
        sc[nt][1] = exp2f((sc[nt][1] - m0) * LOG2E); s0 += sc[nt][1];
        sc[nt][2] = exp2f((sc[nt][2] - m1) * LOG2E); s1 += sc[nt][2];
        sc[nt][3] = exp2f((sc[nt][3] - m1) * LOG2E); s1 += sc[nt][3];
    }
    s0 += __shfl_xor_sync(0xffffffffu, s0, 1);
    s0 += __shfl_xor_sync(0xffffffffu, s0, 2);
    s1 += __shfl_xor_sync(0xffffffffu, s1, 1);
    s1 += __shfl_xor_sync(0xffffffffu, s1, 2);
    const float inv0 = 1.0f / s0, inv1 = 1.0f / s1;
#pragma unroll
    for (int nt = 0; nt < 16; nt++) {
        int n = nt * 8 + 2 * qc;
        Ps[(row + g) * 132 + n] = tf32f(sc[nt][0] * inv0);
        Ps[(row + g) * 132 + n + 1] = tf32f(sc[nt][1] * inv0);
        Ps[(row + g + 8) * 132 + n] = tf32f(sc[nt][2] * inv1);
        Ps[(row + g + 8) * 132 + n + 1] = tf32f(sc[nt][3] * inv1);
    }
    __syncthreads();

    float oa[8][4];
#pragma unroll
    for (int nt = 0; nt < 8; nt++)
#pragma unroll
        for (int k = 0; k < 4; k++) oa[nt][k] = 0.f;
#pragma unroll
    for (int k0 = 0; k0 < 128; k0 += 8) {
        uint32_t a[4];
        a[0] = fu(Ps[(row + g) * 132 + k0 + qc]);
        a[1] = fu(Ps[(row + g + 8) * 132 + k0 + qc]);
        a[2] = fu(Ps[(row + g) * 132 + k0 + qc + 4]);
        a[3] = fu(Ps[(row + g + 8) * 132 + k0 + qc + 4]);
#pragma unroll
        for (int nt = 0; nt < 8; nt++) {
            uint32_t bb[2];
            bb[0] = fu(Vs[(k0 + qc) * 68 + nt * 8 + g]);
            bb[1] = fu(Vs[(k0 + qc + 4) * 68 + nt * 8 + g]);
            mma8(oa[nt], a, bb);
        }
    }
    __syncthreads();
    // stage row-attn out [l][d], stride 65
#pragma unroll
    for (int nt = 0; nt < 8; nt++) {
        int n = nt * 8 + 2 * qc;
        Os[(row + g) * 65 + n] = oa[nt][0];
        Os[(row + g) * 65 + n + 1] = oa[nt][1];
        Os[(row + g + 8) * 65 + n] = oa[nt][2];
        Os[(row + g + 8) * 65 + n + 1] = oa[nt][3];
    }
    __syncthreads();
    // add col-attn scratch (contiguous reads)
#pragma unroll
    for (int rep = 0; rep < 8; rep++) {
        int idx = rep * 256 + tid;
        int l = idx >> 4;
        int d4 = (idx & 15) * 4;
        float4 c4 = *reinterpret_cast<const float4*>(g_oc + rbase + (size_t)idx * 4);
        int so = l * 65 + d4;
        Os[so] += c4.x;
        Os[so + 1] += c4.y;
        Os[so + 2] += c4.z;
        Os[so + 3] += c4.w;
    }
    __syncthreads();
    // transposed, fully coalesced final write: out[b][h*64+d][s][l]
#pragma unroll
    for (int rep = 0; rep < 8; rep++) {
        int idx = rep * 256 + tid;           // 0..2047 = 64 d x 32 l4
        int d = idx >> 5;
        int l4 = (idx & 31) * 4;
        float4 v;
        v.x = Os[(l4 + 0) * 65 + d];
        v.y = Os[(l4 + 1) * 65 + d];
        v.z = Os[(l4 + 2) * 65 + d];
        v.w = Os[(l4 + 3) * 65 + d];
        size_t oaddr = (((size_t)(b * 512 + h * 64 + d)) * 128 + s) * 128 + l4;
        *reinterpret_cast<float4*>(out + oaddr) = v;
    }
}

extern "C" void kernel_launch(void* const* d_in, const int* in_sizes, int n_in,
                              void* d_out, int out_size) {
    const float* x = (const float*)d_in[0];
    const float* W = (const float*)d_in[1];
    const float* bias = (const float*)d_in[2];
    float* out = (float*)d_out;

    cudaFuncSetAttribute(k_qkv, cudaFuncAttributeMaxDynamicSharedMemorySize, K1_SMEM);
    cudaFuncSetAttribute(k_colattn, cudaFuncAttributeMaxDynamicSharedMemorySize, ATTN_SMEM);
    cudaFuncSetAttribute(k_rowattn, cudaFuncAttributeMaxDynamicSharedMemorySize, ATTN_SMEM);

    k_qkv<<<dim3(12, 128, 2), 256, K1_SMEM>>>(x, W, bias);
    k_colattn<<<dim3(128, 8, 2), 256, ATTN_SMEM>>>();
    k_rowattn<<<dim3(128, 8, 2), 256, ATTN_SMEM>>>(out);
}